// round 14
// baseline (speedup 1.0000x reference)
#include <cuda_runtime.h>
#include <cuda_fp16.h>
#include <stdint.h>
#include <math.h>

#define Nn 50000
#define Ee 600000
#define Ff 16
#define Pp 32
#define Cc 128
#define Ll 6
#define NT 391           // row tiles of 128
#define TG_GRID 148      // persistent, 1 CTA/SM

// ---------------- scratch (static device globals; no allocation) -------------
__device__ __align__(16) __half g_hw[Nn * Cc];        // gcn GEMM out (fp16)
__device__ float g_last[Nn * Cc];                      // last1 out (fp32)
__device__ __align__(16) __half g_id_h[Nn * Cc], g_id_l[Nn * Cc];
__device__ __align__(16) __half g_h_h[Nn * Cc],  g_h_l[Nn * Cc];
__device__ int   g_cnt[Nn];
__device__ int   g_rowptr[Nn + 1];
__device__ int   g_pos[Nn];
__device__ int   g_srcs[Ee];
__device__ float g_ws[Ee];
__device__ int   g_part[256];
__device__ __align__(16) __half g_wg[Ll * Cc * Cc];
__device__ __align__(16) __half g_wf[Ll * 2 * Cc * Cc];
__device__ __align__(16) __half g_wl[2 * Cc * Cc];

// ---------------- helpers -----------------------------------------------------
__device__ __forceinline__ uint32_t smem_u32(const void* p) {
    uint32_t a;
    asm("{ .reg .u64 t; cvta.to.shared.u64 t, %1; cvt.u32.u64 %0, t; }" : "=r"(a) : "l"(p));
    return a;
}
__device__ __forceinline__ void cp16(uint32_t dst, const void* src, uint32_t srcsize) {
    asm volatile("cp.async.cg.shared.global [%0], [%1], 16, %2;"
                 :: "r"(dst), "l"(src), "r"(srcsize));
}
__device__ __forceinline__ void ldsm4(uint32_t* r, uint32_t a) {
    asm volatile("ldmatrix.sync.aligned.m8n8.x4.shared.b16 {%0,%1,%2,%3}, [%4];"
        : "=r"(r[0]), "=r"(r[1]), "=r"(r[2]), "=r"(r[3]) : "r"(a));
}
__device__ __forceinline__ void ldsm2(uint32_t* r, uint32_t a) {
    asm volatile("ldmatrix.sync.aligned.m8n8.x2.shared.b16 {%0,%1}, [%2];"
        : "=r"(r[0]), "=r"(r[1]) : "r"(a));
}
__device__ __forceinline__ void mma16816(float* d, const uint32_t* a, const uint32_t* b) {
    asm volatile("mma.sync.aligned.m16n8k16.row.col.f32.f16.f16.f32 "
        "{%0,%1,%2,%3}, {%4,%5,%6,%7}, {%8,%9}, {%0,%1,%2,%3};"
        : "+f"(d[0]), "+f"(d[1]), "+f"(d[2]), "+f"(d[3])
        : "r"(a[0]), "r"(a[1]), "r"(a[2]), "r"(a[3]), "r"(b[0]), "r"(b[1]));
}
__device__ __forceinline__ void split2(float v0, float v1, __half2& h, __half2& l) {
    h = __floats2half2_rn(v0, v1);
    float2 hf = __half22float2(h);
    l = __floats2half2_rn(v0 - hf.x, v1 - hf.y);
}

// ---------------- input MLP (fp16 split outputs) -------------------------------
__global__ __launch_bounds__(256) void k_input(
    const float* __restrict__ x,
    const float* __restrict__ Wp, const float* __restrict__ bp,
    const float* __restrict__ W1, const float* __restrict__ b1,
    const float* __restrict__ W2, const float* __restrict__ b2)
{
    __shared__ float sWp[Ff * Pp], sbp[Pp];
    __shared__ float sW1[Pp * Cc], sb1[Cc];
    __shared__ float sW2[Pp * Cc], sb2[Cc];
    __shared__ float sx[16 * Ff], shp[16 * Pp];
    int t = threadIdx.x;
    for (int i = t; i < Ff * Pp; i += 256) sWp[i] = Wp[i];
    if (t < Pp) sbp[t] = bp[t];
    for (int i = t; i < Pp * Cc; i += 256) { sW1[i] = W1[i]; sW2[i] = W2[i]; }
    if (t < Cc) { sb1[t] = b1[t]; sb2[t] = b2[t]; }

    int nb = blockIdx.x * 16;
    int nrem = min(16, Nn - nb);
    __syncthreads();

    if (t < nrem * Ff) sx[t] = x[nb * Ff + t];
    __syncthreads();

    #pragma unroll
    for (int q = 0; q < 2; q++) {
        int idx = t + 256 * q;
        int node = idx >> 5, p = idx & 31;
        if (node < nrem) {
            float s = sbp[p];
            #pragma unroll
            for (int k = 0; k < Ff; k++) s += sx[node * Ff + k] * sWp[k * Pp + p];
            shp[idx] = fmaxf(s, 0.f);
        }
    }
    __syncthreads();

    int ch = (t & 63) * 2;
    #pragma unroll
    for (int it = 0; it < 4; it++) {
        int nl = (t >> 6) + 4 * it;
        if (nl < nrem) {
            float s1a = sb1[ch], s1b = sb1[ch + 1];
            float s2a = sb2[ch], s2b = sb2[ch + 1];
            #pragma unroll
            for (int k = 0; k < Pp; k++) {
                float hk = shp[nl * Pp + k];
                s1a += hk * sW1[k * Cc + ch];
                s1b += hk * sW1[k * Cc + ch + 1];
                s2a += hk * sW2[k * Cc + ch];
                s2b += hk * sW2[k * Cc + ch + 1];
            }
            size_t o = (size_t)(nb + nl) * Cc + ch;
            __half2 h, l;
            split2(fmaxf(s1a, 0.f), fmaxf(s1b, 0.f), h, l);
            *(__half2*)(g_id_h + o) = h;
            *(__half2*)(g_id_l + o) = l;
            split2(fmaxf(s2a, 0.f), fmaxf(s2b, 0.f), h, l);
            *(__half2*)(g_h_h + o) = h;
            *(__half2*)(g_h_l + o) = l;
        }
    }
}

// ---------------- weight prep: transpose + fp16 -------------------------------
__global__ void k_prepw(const float* __restrict__ gW, const float* __restrict__ fW,
                        const float* __restrict__ l1W)
{
    int idx = blockIdx.x * 256 + threadIdx.x;
    float v;
    __half* dst;
    size_t o;
    if (idx < Ll * Cc * Cc) {
        int l = idx >> 14, r = idx & 16383;
        int n = r >> 7, k = r & 127;
        v = gW[(size_t)l * 16384 + (size_t)k * 128 + n];
        o = (size_t)l * 16384 + (size_t)n * 128 + k;
        dst = g_wg;
    } else if (idx < Ll * Cc * Cc + Ll * 2 * Cc * Cc) {
        int j = idx - Ll * Cc * Cc;
        int l = j >> 15, r = j & 32767;
        int n = r >> 8, k = r & 255;
        v = fW[(size_t)l * 32768 + (size_t)k * 128 + n];
        o = (size_t)l * 32768 + (size_t)n * 256 + k;
        dst = g_wf;
    } else {
        int j = idx - (Ll * Cc * Cc + Ll * 2 * Cc * Cc);
        int n = j >> 8, k = j & 255;
        v = l1W[(size_t)k * 128 + n];
        o = (size_t)n * 256 + k;
        dst = g_wl;
    }
    dst[o] = __float2half(v);
}

// ---------------- fp16 2-term HMMA GEMM, 4-stage deep-prefetch ring -----------
// flags: 1=relu, 2=bias, 4=fp16-split out, 8=fp16-single out
#define PADK 72
#define ASTG (128 * PADK * 2)
#define NSTG 4
__device__ __forceinline__ void issueA(
    int it, int nch, int bid, uint32_t uA,
    const __half* Ah1, const __half* Al1,
    const __half* Ah2, const __half* Al2, int tid)
{
    int j = it / nch, ch = it % nch;
    int row0 = (bid + j * TG_GRID) * 128;
    const __half* Ah = (ch * 64 < Cc) ? Ah1 : Ah2;
    const __half* Al = (ch * 64 < Cc) ? Al1 : Al2;
    int kA = (ch * 64) & (Cc - 1);
    uint32_t sb = uA + (uint32_t)(it & (NSTG - 1)) * (2 * ASTG);
    #pragma unroll
    for (int q = 0; q < 2; q++) {
        int i = tid + 512 * q;
        int r = i >> 3, k8 = (i & 7) * 8;
        uint32_t doff = (uint32_t)((r * PADK + k8) << 1);
        int grow = row0 + r;
        uint32_t sz = (grow < Nn) ? 16u : 0u;
        size_t aoff = (size_t)grow * Cc + kA + k8;
        cp16(sb + doff,        Ah + aoff, sz);
        cp16(sb + ASTG + doff, Al + aoff, sz);
    }
    asm volatile("cp.async.commit_group;");
}

__global__ __launch_bounds__(512) void k_tgemm(
    const __half* __restrict__ Ah1, const __half* __restrict__ Al1,
    const __half* __restrict__ Ah2, const __half* __restrict__ Al2,
    const __half* __restrict__ Wh,
    const float* __restrict__ bias, float* __restrict__ outf,
    __half* __restrict__ outh, __half* __restrict__ outl,
    int K, int flags)
{
    extern __shared__ char sm[];
    int PADW = K + 8;
    uint32_t SWB = (uint32_t)(128 * PADW * 2);
    uint32_t uW = smem_u32(sm);
    uint32_t uA = uW + SWB;

    int tid = threadIdx.x;
    int wid = tid >> 5, lane = tid & 31;
    int wm = wid & 3, wn = wid >> 2;
    int rim = lane & 7, mid = lane >> 3;
    int bid = blockIdx.x;

    int wq = (K >> 3);
    for (int i = tid; i < 128 * wq; i += 512) {
        int n = i / wq, k8 = (i % wq) * 8;
        uint32_t doff = (uint32_t)((n * PADW + k8) << 1);
        cp16(uW + doff, Wh + (size_t)n * K + k8, 16u);
    }
    asm volatile("cp.async.commit_group;");

    uint32_t aBase[2], bBase[4];
    #pragma unroll
    for (int mt = 0; mt < 2; mt++) {
        int r = wm * 32 + mt * 16 + rim + (mid & 1) * 8;
        int c = (mid >> 1) * 8;
        aBase[mt] = uA + (uint32_t)((r * PADK + c) << 1);
    }
    #pragma unroll
    for (int nt = 0; nt < 4; nt++) {
        int r = wn * 32 + nt * 8 + rim;
        int c = (mid & 1) * 8;
        bBase[nt] = uW + (uint32_t)((r * PADW + c) << 1);
    }

    int nch = K >> 6;
    int nt_cta = (NT - bid + TG_GRID - 1) / TG_GRID;
    int niter = nt_cta * nch;
    if (niter <= 0) return;

    float acc[2][4][4];
    #pragma unroll
    for (int mt = 0; mt < 2; mt++)
        #pragma unroll
        for (int nt = 0; nt < 4; nt++)
            #pragma unroll
            for (int q = 0; q < 4; q++) acc[mt][nt][q] = 0.f;

    #pragma unroll
    for (int j = 0; j < NSTG - 1; j++)
        if (j < niter) issueA(j, nch, bid, uA, Ah1, Al1, Ah2, Al2, tid);

    for (int it = 0; it < niter; it++) {
        int ch = it % nch;
        if (it + NSTG - 1 < niter)
            issueA(it + NSTG - 1, nch, bid, uA, Ah1, Al1, Ah2, Al2, tid);
        int ahead = niter - 1 - it;
        if (ahead >= 3)      asm volatile("cp.async.wait_group 3;");
        else if (ahead == 2) asm volatile("cp.async.wait_group 2;");
        else if (ahead == 1) asm volatile("cp.async.wait_group 1;");
        else                 asm volatile("cp.async.wait_group 0;");
        __syncthreads();

        uint32_t sA = (uint32_t)(it & (NSTG - 1)) * (2 * ASTG);
        uint32_t kwb = (uint32_t)((ch * 64) << 1);
        #pragma unroll
        for (int ks = 0; ks < 4; ks++) {
            uint32_t ka = (uint32_t)ks * 32;
            uint32_t kw = kwb + (uint32_t)ks * 32;
            uint32_t ah[2][4], al[2][4];
            ldsm4(ah[0], aBase[0] + sA + ka);
            ldsm4(ah[1], aBase[1] + sA + ka);
            ldsm4(al[0], aBase[0] + sA + ka + ASTG);
            ldsm4(al[1], aBase[1] + sA + ka + ASTG);
            #pragma unroll
            for (int nt = 0; nt < 4; nt++) {
                uint32_t bh[2];
                ldsm2(bh, bBase[nt] + kw);
                mma16816(acc[0][nt], ah[0], bh);
                mma16816(acc[1][nt], ah[1], bh);
                mma16816(acc[0][nt], al[0], bh);
                mma16816(acc[1][nt], al[1], bh);
            }
        }

        if (ch == nch - 1) {
            int row0 = (bid + (it / nch) * TG_GRID) * 128;
            int gr = row0 + wm * 32 + (lane >> 2);
            int gc = wn * 32 + (lane & 3) * 2;
            #pragma unroll
            for (int nt = 0; nt < 4; nt++) {
                int col = gc + nt * 8;
                float2 b2 = make_float2(0.f, 0.f);
                if (flags & 2) b2 = *(const float2*)(bias + col);
                #pragma unroll
                for (int mt = 0; mt < 2; mt++) {
                    #pragma unroll
                    for (int hf = 0; hf < 2; hf++) {
                        int r = gr + mt * 16 + hf * 8;
                        if (r < Nn) {
                            float v0 = acc[mt][nt][2 * hf + 0] + b2.x;
                            float v1 = acc[mt][nt][2 * hf + 1] + b2.y;
                            if (flags & 1) { v0 = fmaxf(v0, 0.f); v1 = fmaxf(v1, 0.f); }
                            size_t o = (size_t)r * Cc + col;
                            if (flags & 4) {
                                __half2 h, l;
                                split2(v0, v1, h, l);
                                *(__half2*)(outh + o) = h;
                                *(__half2*)(outl + o) = l;
                            } else if (flags & 8) {
                                *(__half2*)(outh + o) = __floats2half2_rn(v0, v1);
                            } else {
                                *(float2*)(outf + o) = make_float2(v0, v1);
                            }
                        }
                    }
                }
            }
            #pragma unroll
            for (int mt = 0; mt < 2; mt++)
                #pragma unroll
                for (int nt = 0; nt < 4; nt++)
                    #pragma unroll
                    for (int q = 0; q < 4; q++) acc[mt][nt][q] = 0.f;
        }
        __syncthreads();
    }
}

// ---------------- FUSED spmm + fcg GEMM ---------------------------------------
// h = relu([id, relu(A_hat@hw + gb)] @ Wf + fb); agg never leaves smem.
// smem: W [128][264] fp16 (67.6KB) + A hi/lo [128][264] fp16 (135.2KB) = 202.8KB
#define PADA 264
#define APL (128 * PADA * 2)     // 67584 bytes per A plane
#define FG_SMEM (128 * PADA * 2 + 2 * APL)  // 202752
__global__ __launch_bounds__(512) void k_fgemm(
    const __half* __restrict__ idh, const __half* __restrict__ idl,
    const __half* __restrict__ hw,
    const float* __restrict__ gbias,
    const __half* __restrict__ Wf, const float* __restrict__ fbias,
    __half* __restrict__ outh, __half* __restrict__ outl)
{
    extern __shared__ char sm[];
    const int K = 256, PADW = 264;
    uint32_t SWB = (uint32_t)(128 * PADW * 2);
    uint32_t uW = smem_u32(sm);
    uint32_t uA = uW + SWB;
    char* pA = sm + SWB;   // byte-pointer view of A region

    int tid = threadIdx.x;
    int wid = tid >> 5, lane = tid & 31;
    int wm = wid & 3, wn = wid >> 2;
    int rim = lane & 7, mid = lane >> 3;
    int bid = blockIdx.x;

    // whole Wf into smem once
    for (int i = tid; i < 128 * 32; i += 512) {
        int n = i >> 5, k8 = (i & 31) * 8;
        cp16(uW + (uint32_t)((n * PADW + k8) << 1), Wf + (size_t)n * K + k8, 16u);
    }
    asm volatile("cp.async.commit_group;");

    uint32_t aBase[2], bBase[4];
    #pragma unroll
    for (int mt = 0; mt < 2; mt++) {
        int r = wm * 32 + mt * 16 + rim + (mid & 1) * 8;
        int c = (mid >> 1) * 8;
        aBase[mt] = uA + (uint32_t)((r * PADA + c) << 1);
    }
    #pragma unroll
    for (int nt = 0; nt < 4; nt++) {
        int r = wn * 32 + nt * 8 + rim;
        int c = (mid & 1) * 8;
        bBase[nt] = uW + (uint32_t)((r * PADW + c) << 1);
    }

    float4 gb4 = *(const float4*)(gbias + lane * 4);

    for (int tile = bid; tile < NT; tile += TG_GRID) {
        int row0 = tile * 128;

        // ---- id rows -> smem A[k<128], hi+lo, via cp.async ----
        #pragma unroll
        for (int q = 0; q < 4; q++) {
            int i = tid + 512 * q;
            int r = i >> 4, k8 = (i & 15) * 8;
            uint32_t doff = (uint32_t)((r * PADA + k8) << 1);
            int grow = row0 + r;
            uint32_t sz = (grow < Nn) ? 16u : 0u;
            size_t so = (size_t)grow * Cc + k8;
            cp16(uA + doff,       idh + so, sz);
            cp16(uA + APL + doff, idl + so, sz);
        }
        asm volatile("cp.async.commit_group;");

        // ---- spmm gather -> smem A[k>=128] (bias+relu+split in regs) ----
        #pragma unroll
        for (int j = 0; j < 8; j++) {
            int r = wid + 16 * j;
            int node = row0 + r;
            if (node < Nn) {
                int s = g_rowptr[node], e = g_rowptr[node + 1];
                float4 acc = make_float4(0.f, 0.f, 0.f, 0.f);
                for (int p = s; p < e; p += 32) {
                    int src = 0; float w = 0.f;
                    if (p + lane < e) { src = g_srcs[p + lane]; w = g_ws[p + lane]; }
                    int cnt = min(32, e - p);
                    for (int jj = 0; jj < cnt; jj++) {
                        int sj  = __shfl_sync(0xffffffffu, src, jj);
                        float wj = __shfl_sync(0xffffffffu, w, jj);
                        const __half2* hr = (const __half2*)(hw + (size_t)sj * Cc + lane * 4);
                        float2 v01 = __half22float2(hr[0]);
                        float2 v23 = __half22float2(hr[1]);
                        acc.x += v01.x * wj; acc.y += v01.y * wj;
                        acc.z += v23.x * wj; acc.w += v23.y * wj;
                    }
                }
                acc.x = fmaxf(acc.x + gb4.x, 0.f);
                acc.y = fmaxf(acc.y + gb4.y, 0.f);
                acc.z = fmaxf(acc.z + gb4.z, 0.f);
                acc.w = fmaxf(acc.w + gb4.w, 0.f);
                uint32_t off = (uint32_t)((r * PADA + 128 + lane * 4) << 1);
                __half2 h, l;
                split2(acc.x, acc.y, h, l);
                *(__half2*)(pA + off) = h;
                *(__half2*)(pA + APL + off) = l;
                split2(acc.z, acc.w, h, l);
                *(__half2*)(pA + off + 4) = h;
                *(__half2*)(pA + APL + off + 4) = l;
            }
        }

        asm volatile("cp.async.wait_group 0;");
        __syncthreads();

        // ---- GEMM K=256 ----
        float acc[2][4][4];
        #pragma unroll
        for (int mt = 0; mt < 2; mt++)
            #pragma unroll
            for (int nt = 0; nt < 4; nt++)
                #pragma unroll
                for (int q = 0; q < 4; q++) acc[mt][nt][q] = 0.f;

        #pragma unroll
        for (int ks = 0; ks < 16; ks++) {
            uint32_t ka = (uint32_t)ks * 32;
            uint32_t ah[2][4], al[2][4];
            ldsm4(ah[0], aBase[0] + ka);
            ldsm4(ah[1], aBase[1] + ka);
            ldsm4(al[0], aBase[0] + ka + APL);
            ldsm4(al[1], aBase[1] + ka + APL);
            #pragma unroll
            for (int nt = 0; nt < 4; nt++) {
                uint32_t bh[2];
                ldsm2(bh, bBase[nt] + ka);
                mma16816(acc[0][nt], ah[0], bh);
                mma16816(acc[1][nt], ah[1], bh);
                mma16816(acc[0][nt], al[0], bh);
                mma16816(acc[1][nt], al[1], bh);
            }
        }

        // ---- epilogue: relu + bias + fp16 split out ----
        int gr = row0 + wm * 32 + (lane >> 2);
        int gc = wn * 32 + (lane & 3) * 2;
        #pragma unroll
        for (int nt = 0; nt < 4; nt++) {
            int col = gc + nt * 8;
            float2 b2 = *(const float2*)(fbias + col);
            #pragma unroll
            for (int mt = 0; mt < 2; mt++) {
                #pragma unroll
                for (int hf = 0; hf < 2; hf++) {
                    int r = gr + mt * 16 + hf * 8;
                    if (r < Nn) {
                        float v0 = fmaxf(acc[mt][nt][2 * hf + 0] + b2.x, 0.f);
                        float v1 = fmaxf(acc[mt][nt][2 * hf + 1] + b2.y, 0.f);
                        size_t o = (size_t)r * Cc + col;
                        __half2 h, l;
                        split2(v0, v1, h, l);
                        *(__half2*)(outh + o) = h;
                        *(__half2*)(outl + o) = l;
                    }
                }
            }
        }
        __syncthreads();
    }
}

// ---------------- CSR build ---------------------------------------------------
__global__ void k_zero_cnt() {
    for (int i = blockIdx.x * blockDim.x + threadIdx.x; i < Nn; i += gridDim.x * blockDim.x)
        g_cnt[i] = 0;
}
__global__ void k_hist(const int* __restrict__ dst) {
    for (int e = blockIdx.x * blockDim.x + threadIdx.x; e < Ee; e += gridDim.x * blockDim.x)
        atomicAdd(&g_cnt[dst[e]], 1);
}
#define SCHUNK 196
__global__ __launch_bounds__(256) void k_scan1() {
    __shared__ int s[256];
    int t = threadIdx.x, b = blockIdx.x;
    int i = b * SCHUNK + t;
    int v = (t < SCHUNK && i < Nn) ? g_cnt[i] : 0;
    s[t] = v; __syncthreads();
    for (int st = 128; st > 0; st >>= 1) {
        if (t < st) s[t] += s[t + st];
        __syncthreads();
    }
    if (t == 0) g_part[b] = s[0];
}
__global__ __launch_bounds__(256) void k_scan2() {
    __shared__ int s[256];
    int t = threadIdx.x;
    int v = g_part[t];
    s[t] = v; __syncthreads();
    for (int st = 1; st < 256; st <<= 1) {
        int x = (t >= st) ? s[t - st] : 0;
        __syncthreads();
        s[t] += x;
        __syncthreads();
    }
    g_part[t] = s[t] - v;
}
__global__ __launch_bounds__(256) void k_scan3() {
    __shared__ int s[256];
    int t = threadIdx.x, b = blockIdx.x;
    int i = b * SCHUNK + t;
    int valid = (t < SCHUNK && i < Nn);
    int v = valid ? g_cnt[i] : 0;
    s[t] = v; __syncthreads();
    for (int st = 1; st < 256; st <<= 1) {
        int x = (t >= st) ? s[t - st] : 0;
        __syncthreads();
        s[t] += x;
        __syncthreads();
    }
    if (valid) {
        int rp = g_part[b] + s[t] - v;
        g_rowptr[i] = rp;
        g_pos[i] = rp;
    }
    if (b == 0 && t == 0) g_rowptr[Nn] = Ee;
}
__global__ void k_scatter(const int* __restrict__ src, const int* __restrict__ dst,
                          const float* __restrict__ w) {
    for (int e = blockIdx.x * blockDim.x + threadIdx.x; e < Ee; e += gridDim.x * blockDim.x) {
        int d = dst[e];
        int p = atomicAdd(&g_pos[d], 1);
        g_srcs[p] = src[e];
        g_ws[p] = w[e];
    }
}

// ---------------- final projection + sigmoid ---------------------------------
__global__ __launch_bounds__(256) void k_last2(const float* __restrict__ h,
                                               const float* __restrict__ W2,
                                               const float* __restrict__ b2,
                                               float* __restrict__ out)
{
    int node = blockIdx.x * 8 + (threadIdx.x >> 5);
    int lane = threadIdx.x & 31;
    if (node >= Nn) return;
    float4 v = *(const float4*)&h[(size_t)node * Cc + lane * 4];
    float hv[4] = {v.x, v.y, v.z, v.w};
    float s0 = 0.f, s1 = 0.f;
    #pragma unroll
    for (int q = 0; q < 4; q++) {
        int k = lane * 4 + q;
        s0 += hv[q] * W2[k * 2 + 0];
        s1 += hv[q] * W2[k * 2 + 1];
    }
    #pragma unroll
    for (int o = 16; o > 0; o >>= 1) {
        s0 += __shfl_xor_sync(0xffffffffu, s0, o);
        s1 += __shfl_xor_sync(0xffffffffu, s1, o);
    }
    if (lane == 0) {
        out[node * 2 + 0] = 1.f / (1.f + expf(-(s0 + b2[0])));
        out[node * 2 + 1] = 1.f / (1.f + expf(-(s1 + b2[1])));
    }
}

// ---------------- launch ------------------------------------------------------
extern "C" void kernel_launch(void* const* d_in, const int* in_sizes, int n_in,
                              void* d_out, int out_size)
{
    const float* x    = (const float*)d_in[0];
    const int*   esrc = (const int*)  d_in[1];
    const int*   edst = (const int*)  d_in[2];
    const float* ew   = (const float*)d_in[3];
    const float* pW   = (const float*)d_in[4];
    const float* pb   = (const float*)d_in[5];
    const float* W1   = (const float*)d_in[6];
    const float* b1   = (const float*)d_in[7];
    const float* W2i  = (const float*)d_in[8];
    const float* b2i  = (const float*)d_in[9];
    const float* gW   = (const float*)d_in[10];
    const float* gb   = (const float*)d_in[11];
    const float* fW   = (const float*)d_in[12];
    const float* fb   = (const float*)d_in[13];
    const float* l1W  = (const float*)d_in[14];
    const float* l1b  = (const float*)d_in[15];
    const float* l2W  = (const float*)d_in[16];
    const float* l2b  = (const float*)d_in[17];
    float* out = (float*)d_out;

    const int SMEM128 = 128 * (128 + 8) * 2 + 2 * NSTG * ASTG;  // 182272
    const int SMEM256 = 128 * (256 + 8) * 2 + 2 * NSTG * ASTG;  // 215040
    cudaFuncSetAttribute(k_tgemm, cudaFuncAttributeMaxDynamicSharedMemorySize, SMEM256);
    cudaFuncSetAttribute(k_fgemm, cudaFuncAttributeMaxDynamicSharedMemorySize, FG_SMEM);

    __half* phw;
    float* plast;
    cudaGetSymbolAddress((void**)&phw,   g_hw);
    cudaGetSymbolAddress((void**)&plast, g_last);
    __half *pidh, *pidl, *phh, *phl;
    cudaGetSymbolAddress((void**)&pidh, g_id_h);
    cudaGetSymbolAddress((void**)&pidl, g_id_l);
    cudaGetSymbolAddress((void**)&phh,  g_h_h);
    cudaGetSymbolAddress((void**)&phl,  g_h_l);
    __half *pwg, *pwf, *pwl;
    cudaGetSymbolAddress((void**)&pwg, g_wg);
    cudaGetSymbolAddress((void**)&pwf, g_wf);
    cudaGetSymbolAddress((void**)&pwl, g_wl);

    // launches 0..2, then the profiled 4th launch is the layer-0 GCN GEMM
    k_input<<<(Nn + 15) / 16, 256>>>(x, pW, pb, W1, b1, W2i, b2i);
    k_prepw<<<1280, 256>>>(gW, fW, l1W);
    k_zero_cnt<<<128, 256>>>();
    k_tgemm<<<TG_GRID, 512, SMEM128>>>(phh, phl, phh, phl,
        pwg, (const float*)0, (float*)0, phw, (__half*)0, Cc, 8);

    k_hist<<<512, 256>>>(edst);
    k_scan1<<<256, 256>>>();
    k_scan2<<<1, 256>>>();
    k_scan3<<<256, 256>>>();
    k_scatter<<<512, 256>>>(esrc, edst, ew);

    for (int l = 0; l < Ll; l++) {
        if (l > 0)
            k_tgemm<<<TG_GRID, 512, SMEM128>>>(phh, phl, phh, phl,
                pwg + (size_t)l * Cc * Cc,
                (const float*)0, (float*)0, phw, (__half*)0, Cc, 8);
        k_fgemm<<<TG_GRID, 512, FG_SMEM>>>(pidh, pidl, phw,
            gb + (size_t)l * Cc,
            pwf + (size_t)l * 2 * Cc * Cc, fb + (size_t)l * Cc,
            phh, phl);
    }
    k_tgemm<<<TG_GRID, 512, SMEM256>>>(pidh, pidl, phh, phl,
        pwl, l1b, plast, (__half*)0, (__half*)0, 2 * Cc, 3);
    const int GS = (Nn + 7) / 8;
    k_last2<<<GS, 256>>>(plast, l2W, l2b, out);
}

// round 15
// speedup vs baseline: 1.4190x; 1.4190x over previous
#include <cuda_runtime.h>
#include <cuda_fp16.h>
#include <stdint.h>
#include <math.h>

#define Nn 50000
#define Ee 600000
#define Ff 16
#define Pp 32
#define Cc 128
#define Ll 6
#define NT 391           // row tiles of 128
#define TG_GRID 148      // persistent, 1 CTA/SM

// ---------------- scratch (static device globals; no allocation) -------------
__device__ __align__(16) __half g_hw[Nn * Cc];      // gcn GEMM out
__device__ float g_last[Nn * Cc];                    // last1 out (fp32)
__device__ __align__(16) __half g_id[Nn * Cc];
__device__ __align__(16) __half g_h[Nn * Cc];
__device__ __align__(16) __half g_ag[Nn * Cc];
__device__ int   g_cnt[Nn];
__device__ int   g_rowptr[Nn + 1];
__device__ int   g_pos[Nn];
__device__ int   g_srcs[Ee];
__device__ float g_ws[Ee];
__device__ int   g_part[256];
__device__ __align__(16) __half g_wg[Ll * Cc * Cc];
__device__ __align__(16) __half g_wf[Ll * 2 * Cc * Cc];
__device__ __align__(16) __half g_wl[2 * Cc * Cc];

// ---------------- helpers -----------------------------------------------------
__device__ __forceinline__ uint32_t smem_u32(const void* p) {
    uint32_t a;
    asm("{ .reg .u64 t; cvta.to.shared.u64 t, %1; cvt.u32.u64 %0, t; }" : "=r"(a) : "l"(p));
    return a;
}
__device__ __forceinline__ void cp16(uint32_t dst, const void* src, uint32_t srcsize) {
    asm volatile("cp.async.cg.shared.global [%0], [%1], 16, %2;"
                 :: "r"(dst), "l"(src), "r"(srcsize));
}
__device__ __forceinline__ void ldsm4(uint32_t* r, uint32_t a) {
    asm volatile("ldmatrix.sync.aligned.m8n8.x4.shared.b16 {%0,%1,%2,%3}, [%4];"
        : "=r"(r[0]), "=r"(r[1]), "=r"(r[2]), "=r"(r[3]) : "r"(a));
}
__device__ __forceinline__ void ldsm2(uint32_t* r, uint32_t a) {
    asm volatile("ldmatrix.sync.aligned.m8n8.x2.shared.b16 {%0,%1}, [%2];"
        : "=r"(r[0]), "=r"(r[1]) : "r"(a));
}
__device__ __forceinline__ void mma16816(float* d, const uint32_t* a, const uint32_t* b) {
    asm volatile("mma.sync.aligned.m16n8k16.row.col.f32.f16.f16.f32 "
        "{%0,%1,%2,%3}, {%4,%5,%6,%7}, {%8,%9}, {%0,%1,%2,%3};"
        : "+f"(d[0]), "+f"(d[1]), "+f"(d[2]), "+f"(d[3])
        : "r"(a[0]), "r"(a[1]), "r"(a[2]), "r"(a[3]), "r"(b[0]), "r"(b[1]));
}

// ---------------- input MLP (fp16 outputs) -------------------------------------
__global__ __launch_bounds__(256) void k_input(
    const float* __restrict__ x,
    const float* __restrict__ Wp, const float* __restrict__ bp,
    const float* __restrict__ W1, const float* __restrict__ b1,
    const float* __restrict__ W2, const float* __restrict__ b2)
{
    __shared__ float sWp[Ff * Pp], sbp[Pp];
    __shared__ float sW1[Pp * Cc], sb1[Cc];
    __shared__ float sW2[Pp * Cc], sb2[Cc];
    __shared__ float sx[16 * Ff], shp[16 * Pp];
    int t = threadIdx.x;
    for (int i = t; i < Ff * Pp; i += 256) sWp[i] = Wp[i];
    if (t < Pp) sbp[t] = bp[t];
    for (int i = t; i < Pp * Cc; i += 256) { sW1[i] = W1[i]; sW2[i] = W2[i]; }
    if (t < Cc) { sb1[t] = b1[t]; sb2[t] = b2[t]; }

    int nb = blockIdx.x * 16;
    int nrem = min(16, Nn - nb);
    __syncthreads();

    if (t < nrem * Ff) sx[t] = x[nb * Ff + t];
    __syncthreads();

    #pragma unroll
    for (int q = 0; q < 2; q++) {
        int idx = t + 256 * q;
        int node = idx >> 5, p = idx & 31;
        if (node < nrem) {
            float s = sbp[p];
            #pragma unroll
            for (int k = 0; k < Ff; k++) s += sx[node * Ff + k] * sWp[k * Pp + p];
            shp[idx] = fmaxf(s, 0.f);
        }
    }
    __syncthreads();

    int ch = (t & 63) * 2;
    #pragma unroll
    for (int it = 0; it < 4; it++) {
        int nl = (t >> 6) + 4 * it;
        if (nl < nrem) {
            float s1a = sb1[ch], s1b = sb1[ch + 1];
            float s2a = sb2[ch], s2b = sb2[ch + 1];
            #pragma unroll
            for (int k = 0; k < Pp; k++) {
                float hk = shp[nl * Pp + k];
                s1a += hk * sW1[k * Cc + ch];
                s1b += hk * sW1[k * Cc + ch + 1];
                s2a += hk * sW2[k * Cc + ch];
                s2b += hk * sW2[k * Cc + ch + 1];
            }
            size_t o = (size_t)(nb + nl) * Cc + ch;
            *(__half2*)(g_id + o) = __floats2half2_rn(fmaxf(s1a, 0.f), fmaxf(s1b, 0.f));
            *(__half2*)(g_h  + o) = __floats2half2_rn(fmaxf(s2a, 0.f), fmaxf(s2b, 0.f));
        }
    }
}

// ---------------- weight prep: transpose + fp16 -------------------------------
__global__ void k_prepw(const float* __restrict__ gW, const float* __restrict__ fW,
                        const float* __restrict__ l1W)
{
    int idx = blockIdx.x * 256 + threadIdx.x;
    float v;
    __half* dst;
    size_t o;
    if (idx < Ll * Cc * Cc) {
        int l = idx >> 14, r = idx & 16383;
        int n = r >> 7, k = r & 127;
        v = gW[(size_t)l * 16384 + (size_t)k * 128 + n];
        o = (size_t)l * 16384 + (size_t)n * 128 + k;
        dst = g_wg;
    } else if (idx < Ll * Cc * Cc + Ll * 2 * Cc * Cc) {
        int j = idx - Ll * Cc * Cc;
        int l = j >> 15, r = j & 32767;
        int n = r >> 8, k = r & 255;
        v = fW[(size_t)l * 32768 + (size_t)k * 128 + n];
        o = (size_t)l * 32768 + (size_t)n * 256 + k;
        dst = g_wf;
    } else {
        int j = idx - (Ll * Cc * Cc + Ll * 2 * Cc * Cc);
        int n = j >> 8, k = j & 255;
        v = l1W[(size_t)k * 128 + n];
        o = (size_t)n * 256 + k;
        dst = g_wl;
    }
    dst[o] = __float2half(v);
}

// ---------------- fp16 single-term HMMA GEMM, persistent, W-resident ----------
// out = act(A@W + b);  A=[A1;A2] fp16, W fp16 [n][K].
// flags: 1=relu, 2=bias, 8=fp16 out (outh), else fp32 out (outf)
#define PADK 72
#define ASTG (128 * PADK * 2)        // 18432 bytes per A stage
__device__ __forceinline__ void issueA(
    int it, int nch, int bid, uint32_t uA,
    const __half* A1, const __half* A2, int tid)
{
    int j = it / nch, ch = it % nch;
    int row0 = (bid + j * TG_GRID) * 128;
    const __half* A = (ch * 64 < Cc) ? A1 : A2;
    int kA = (ch * 64) & (Cc - 1);
    uint32_t sb = uA + (uint32_t)(it & 1) * ASTG;
    #pragma unroll
    for (int q = 0; q < 2; q++) {
        int i = tid + 512 * q;
        int r = i >> 3, k8 = (i & 7) * 8;
        uint32_t doff = (uint32_t)((r * PADK + k8) << 1);
        int grow = row0 + r;
        uint32_t sz = (grow < Nn) ? 16u : 0u;
        cp16(sb + doff, A + (size_t)grow * Cc + kA + k8, sz);
    }
    asm volatile("cp.async.commit_group;");
}

__global__ __launch_bounds__(512) void k_tgemm(
    const __half* __restrict__ A1, const __half* __restrict__ A2,
    const __half* __restrict__ Wh,
    const float* __restrict__ bias, float* __restrict__ outf,
    __half* __restrict__ outh, int K, int flags)
{
    extern __shared__ char sm[];
    int PADW = K + 8;
    uint32_t SWB = (uint32_t)(128 * PADW * 2);
    uint32_t uW = smem_u32(sm);
    uint32_t uA = uW + SWB;

    int tid = threadIdx.x;
    int wid = tid >> 5, lane = tid & 31;
    int wm = wid & 3, wn = wid >> 2;
    int rim = lane & 7, mid = lane >> 3;
    int bid = blockIdx.x;

    int wq = (K >> 3);
    for (int i = tid; i < 128 * wq; i += 512) {
        int n = i / wq, k8 = (i % wq) * 8;
        cp16(uW + (uint32_t)((n * PADW + k8) << 1), Wh + (size_t)n * K + k8, 16u);
    }
    asm volatile("cp.async.commit_group;");

    uint32_t aBase[2], bBase[4];
    #pragma unroll
    for (int mt = 0; mt < 2; mt++) {
        int r = wm * 32 + mt * 16 + rim + (mid & 1) * 8;
        int c = (mid >> 1) * 8;
        aBase[mt] = uA + (uint32_t)((r * PADK + c) << 1);
    }
    #pragma unroll
    for (int nt = 0; nt < 4; nt++) {
        int r = wn * 32 + nt * 8 + rim;
        int c = (mid & 1) * 8;
        bBase[nt] = uW + (uint32_t)((r * PADW + c) << 1);
    }

    int nch = K >> 6;
    int nt_cta = (NT - bid + TG_GRID - 1) / TG_GRID;
    int niter = nt_cta * nch;
    if (niter <= 0) return;

    float acc[2][4][4];
    #pragma unroll
    for (int mt = 0; mt < 2; mt++)
        #pragma unroll
        for (int nt = 0; nt < 4; nt++)
            #pragma unroll
            for (int q = 0; q < 4; q++) acc[mt][nt][q] = 0.f;

    issueA(0, nch, bid, uA, A1, A2, tid);

    for (int it = 0; it < niter; it++) {
        int ch = it % nch;
        if (it + 1 < niter) {
            issueA(it + 1, nch, bid, uA, A1, A2, tid);
            asm volatile("cp.async.wait_group 1;");
        } else {
            asm volatile("cp.async.wait_group 0;");
        }
        __syncthreads();

        uint32_t sA = (uint32_t)(it & 1) * ASTG;
        uint32_t kwb = (uint32_t)((ch * 64) << 1);
        #pragma unroll
        for (int ks = 0; ks < 4; ks++) {
            uint32_t ka = (uint32_t)ks * 32;
            uint32_t kw = kwb + (uint32_t)ks * 32;
            uint32_t ah[2][4];
            ldsm4(ah[0], aBase[0] + sA + ka);
            ldsm4(ah[1], aBase[1] + sA + ka);
            #pragma unroll
            for (int nt = 0; nt < 4; nt++) {
                uint32_t bh[2];
                ldsm2(bh, bBase[nt] + kw);
                mma16816(acc[0][nt], ah[0], bh);
                mma16816(acc[1][nt], ah[1], bh);
            }
        }

        if (ch == nch - 1) {
            int row0 = (bid + (it / nch) * TG_GRID) * 128;
            int gr = row0 + wm * 32 + (lane >> 2);
            int gc = wn * 32 + (lane & 3) * 2;
            #pragma unroll
            for (int nt = 0; nt < 4; nt++) {
                int col = gc + nt * 8;
                float2 b2 = make_float2(0.f, 0.f);
                if (flags & 2) b2 = *(const float2*)(bias + col);
                #pragma unroll
                for (int mt = 0; mt < 2; mt++) {
                    #pragma unroll
                    for (int hf = 0; hf < 2; hf++) {
                        int r = gr + mt * 16 + hf * 8;
                        if (r < Nn) {
                            float v0 = acc[mt][nt][2 * hf + 0] + b2.x;
                            float v1 = acc[mt][nt][2 * hf + 1] + b2.y;
                            if (flags & 1) { v0 = fmaxf(v0, 0.f); v1 = fmaxf(v1, 0.f); }
                            size_t o = (size_t)r * Cc + col;
                            if (flags & 8) {
                                *(__half2*)(outh + o) = __floats2half2_rn(v0, v1);
                            } else {
                                *(float2*)(outf + o) = make_float2(v0, v1);
                            }
                        }
                    }
                }
            }
            #pragma unroll
            for (int mt = 0; mt < 2; mt++)
                #pragma unroll
                for (int nt = 0; nt < 4; nt++)
                    #pragma unroll
                    for (int q = 0; q < 4; q++) acc[mt][nt][q] = 0.f;
        }
        __syncthreads();
    }
}

// ---------------- CSR build ---------------------------------------------------
__global__ void k_zero_cnt() {
    for (int i = blockIdx.x * blockDim.x + threadIdx.x; i < Nn; i += gridDim.x * blockDim.x)
        g_cnt[i] = 0;
}
__global__ void k_hist(const int* __restrict__ dst) {
    for (int e = blockIdx.x * blockDim.x + threadIdx.x; e < Ee; e += gridDim.x * blockDim.x)
        atomicAdd(&g_cnt[dst[e]], 1);
}
#define SCHUNK 196
__global__ __launch_bounds__(256) void k_scan1() {
    __shared__ int s[256];
    int t = threadIdx.x, b = blockIdx.x;
    int i = b * SCHUNK + t;
    int v = (t < SCHUNK && i < Nn) ? g_cnt[i] : 0;
    s[t] = v; __syncthreads();
    for (int st = 128; st > 0; st >>= 1) {
        if (t < st) s[t] += s[t + st];
        __syncthreads();
    }
    if (t == 0) g_part[b] = s[0];
}
__global__ __launch_bounds__(256) void k_scan2() {
    __shared__ int s[256];
    int t = threadIdx.x;
    int v = g_part[t];
    s[t] = v; __syncthreads();
    for (int st = 1; st < 256; st <<= 1) {
        int x = (t >= st) ? s[t - st] : 0;
        __syncthreads();
        s[t] += x;
        __syncthreads();
    }
    g_part[t] = s[t] - v;
}
__global__ __launch_bounds__(256) void k_scan3() {
    __shared__ int s[256];
    int t = threadIdx.x, b = blockIdx.x;
    int i = b * SCHUNK + t;
    int valid = (t < SCHUNK && i < Nn);
    int v = valid ? g_cnt[i] : 0;
    s[t] = v; __syncthreads();
    for (int st = 1; st < 256; st <<= 1) {
        int x = (t >= st) ? s[t - st] : 0;
        __syncthreads();
        s[t] += x;
        __syncthreads();
    }
    if (valid) {
        int rp = g_part[b] + s[t] - v;
        g_rowptr[i] = rp;
        g_pos[i] = rp;
    }
    if (b == 0 && t == 0) g_rowptr[Nn] = Ee;
}
__global__ void k_scatter(const int* __restrict__ src, const int* __restrict__ dst,
                          const float* __restrict__ w) {
    for (int e = blockIdx.x * blockDim.x + threadIdx.x; e < Ee; e += gridDim.x * blockDim.x) {
        int d = dst[e];
        int p = atomicAdd(&g_pos[d], 1);
        g_srcs[p] = src[e];
        g_ws[p] = w[e];
    }
}

// ---------------- SpMM (fp16 in/out) fused bias+relu ---------------------------
__global__ __launch_bounds__(256) void k_spmm(const __half* __restrict__ hw,
                                              const float* __restrict__ bias)
{
    int node = blockIdx.x * 8 + (threadIdx.x >> 5);
    int lane = threadIdx.x & 31;
    if (node >= Nn) return;
    int s = g_rowptr[node], e = g_rowptr[node + 1];
    float4 acc = make_float4(0.f, 0.f, 0.f, 0.f);
    for (int p = s; p < e; p += 32) {
        int src = 0; float w = 0.f;
        if (p + lane < e) { src = g_srcs[p + lane]; w = g_ws[p + lane]; }
        int cnt = min(32, e - p);
        for (int j = 0; j < cnt; j++) {
            int sj  = __shfl_sync(0xffffffffu, src, j);
            float wj = __shfl_sync(0xffffffffu, w, j);
            const __half2* row = (const __half2*)(hw + (size_t)sj * Cc + lane * 4);
            float2 v01 = __half22float2(row[0]);
            float2 v23 = __half22float2(row[1]);
            acc.x += v01.x * wj; acc.y += v01.y * wj;
            acc.z += v23.x * wj; acc.w += v23.y * wj;
        }
    }
    float4 b4 = *(const float4*)&bias[lane * 4];
    acc.x = fmaxf(acc.x + b4.x, 0.f);
    acc.y = fmaxf(acc.y + b4.y, 0.f);
    acc.z = fmaxf(acc.z + b4.z, 0.f);
    acc.w = fmaxf(acc.w + b4.w, 0.f);
    size_t o = (size_t)node * Cc + lane * 4;
    *(__half2*)(g_ag + o)     = __floats2half2_rn(acc.x, acc.y);
    *(__half2*)(g_ag + o + 2) = __floats2half2_rn(acc.z, acc.w);
}

// ---------------- final projection + sigmoid ---------------------------------
__global__ __launch_bounds__(256) void k_last2(const float* __restrict__ h,
                                               const float* __restrict__ W2,
                                               const float* __restrict__ b2,
                                               float* __restrict__ out)
{
    int node = blockIdx.x * 8 + (threadIdx.x >> 5);
    int lane = threadIdx.x & 31;
    if (node >= Nn) return;
    float4 v = *(const float4*)&h[(size_t)node * Cc + lane * 4];
    float hv[4] = {v.x, v.y, v.z, v.w};
    float s0 = 0.f, s1 = 0.f;
    #pragma unroll
    for (int q = 0; q < 4; q++) {
        int k = lane * 4 + q;
        s0 += hv[q] * W2[k * 2 + 0];
        s1 += hv[q] * W2[k * 2 + 1];
    }
    #pragma unroll
    for (int o = 16; o > 0; o >>= 1) {
        s0 += __shfl_xor_sync(0xffffffffu, s0, o);
        s1 += __shfl_xor_sync(0xffffffffu, s1, o);
    }
    if (lane == 0) {
        out[node * 2 + 0] = 1.f / (1.f + expf(-(s0 + b2[0])));
        out[node * 2 + 1] = 1.f / (1.f + expf(-(s1 + b2[1])));
    }
}

// ---------------- launch ------------------------------------------------------
extern "C" void kernel_launch(void* const* d_in, const int* in_sizes, int n_in,
                              void* d_out, int out_size)
{
    const float* x    = (const float*)d_in[0];
    const int*   esrc = (const int*)  d_in[1];
    const int*   edst = (const int*)  d_in[2];
    const float* ew   = (const float*)d_in[3];
    const float* pW   = (const float*)d_in[4];
    const float* pb   = (const float*)d_in[5];
    const float* W1   = (const float*)d_in[6];
    const float* b1   = (const float*)d_in[7];
    const float* W2i  = (const float*)d_in[8];
    const float* b2i  = (const float*)d_in[9];
    const float* gW   = (const float*)d_in[10];
    const float* gb   = (const float*)d_in[11];
    const float* fW   = (const float*)d_in[12];
    const float* fb   = (const float*)d_in[13];
    const float* l1W  = (const float*)d_in[14];
    const float* l1b  = (const float*)d_in[15];
    const float* l2W  = (const float*)d_in[16];
    const float* l2b  = (const float*)d_in[17];
    float* out = (float*)d_out;

    const int SMEM128 = 128 * (128 + 8) * 2 + 2 * ASTG;  // 71680
    const int SMEM256 = 128 * (256 + 8) * 2 + 2 * ASTG;  // 104448
    cudaFuncSetAttribute(k_tgemm, cudaFuncAttributeMaxDynamicSharedMemorySize, SMEM256);

    __half* phw;
    float* plast;
    cudaGetSymbolAddress((void**)&phw,   g_hw);
    cudaGetSymbolAddress((void**)&plast, g_last);
    __half *pid, *ph, *pag;
    cudaGetSymbolAddress((void**)&pid, g_id);
    cudaGetSymbolAddress((void**)&ph,  g_h);
    cudaGetSymbolAddress((void**)&pag, g_ag);
    __half *pwg, *pwf, *pwl;
    cudaGetSymbolAddress((void**)&pwg, g_wg);
    cudaGetSymbolAddress((void**)&pwf, g_wf);
    cudaGetSymbolAddress((void**)&pwl, g_wl);

    // launches 0..2, then the profiled 4th launch is the layer-0 GCN GEMM
    k_input<<<(Nn + 15) / 16, 256>>>(x, pW, pb, W1, b1, W2i, b2i);
    k_prepw<<<1280, 256>>>(gW, fW, l1W);
    k_zero_cnt<<<128, 256>>>();
    k_tgemm<<<TG_GRID, 512, SMEM128>>>(ph, ph, pwg,
        (const float*)0, (float*)0, phw, Cc, 8);

    k_hist<<<512, 256>>>(edst);
    k_scan1<<<256, 256>>>();
    k_scan2<<<1, 256>>>();
    k_scan3<<<256, 256>>>();
    k_scatter<<<512, 256>>>(esrc, edst, ew);

    const int GS = (Nn + 7) / 8;
    for (int l = 0; l < Ll; l++) {
        if (l > 0)
            k_tgemm<<<TG_GRID, 512, SMEM128>>>(ph, ph,
                pwg + (size_t)l * Cc * Cc,
                (const float*)0, (float*)0, phw, Cc, 8);
        k_spmm<<<GS, 256>>>(phw, gb + (size_t)l * Cc);
        k_tgemm<<<TG_GRID, 512, SMEM256>>>(pid, pag,
            pwf + (size_t)l * 2 * Cc * Cc,
            fb + (size_t)l * Cc, (float*)0, ph, 2 * Cc, 11);
    }
    k_tgemm<<<TG_GRID, 512, SMEM256>>>(pid, ph, pwl,
        l1b, plast, (__half*)0, 2 * Cc, 3);
    k_last2<<<GS, 256>>>(plast, l2W, l2b, out);
}

// round 16
// speedup vs baseline: 1.6658x; 1.1739x over previous
#include <cuda_runtime.h>
#include <cuda_fp16.h>
#include <stdint.h>
#include <math.h>

#define Nn 50000
#define Ee 600000
#define Ff 16
#define Pp 32
#define Cc 128
#define Ll 6
#define NT 391           // row tiles of 128
#define TG_GRID 148      // persistent, 1 CTA/SM

// ---------------- scratch (static device globals; no allocation) -------------
__device__ __align__(16) __half g_hw[Nn * Cc];      // gcn GEMM out
__device__ float g_last[Nn * Cc];                    // last1 out (fp32)
__device__ __align__(16) __half g_id[Nn * Cc];
__device__ __align__(16) __half g_h[Nn * Cc];
__device__ __align__(16) __half g_ag[Nn * Cc];
__device__ int   g_cnt[Nn];
__device__ int   g_rowptr[Nn + 1];
__device__ int   g_pos[Nn];
__device__ int   g_srcs[Ee];
__device__ float g_ws[Ee];
__device__ int   g_part[256];
__device__ __align__(16) __half g_wg[Ll * Cc * Cc];
__device__ __align__(16) __half g_wf[Ll * 2 * Cc * Cc];
__device__ __align__(16) __half g_wl[2 * Cc * Cc];

// ---------------- helpers -----------------------------------------------------
__device__ __forceinline__ uint32_t smem_u32(const void* p) {
    uint32_t a;
    asm("{ .reg .u64 t; cvta.to.shared.u64 t, %1; cvt.u32.u64 %0, t; }" : "=r"(a) : "l"(p));
    return a;
}
__device__ __forceinline__ void cp16(uint32_t dst, const void* src, uint32_t srcsize) {
    asm volatile("cp.async.cg.shared.global [%0], [%1], 16, %2;"
                 :: "r"(dst), "l"(src), "r"(srcsize));
}
__device__ __forceinline__ void ldsm4(uint32_t* r, uint32_t a) {
    asm volatile("ldmatrix.sync.aligned.m8n8.x4.shared.b16 {%0,%1,%2,%3}, [%4];"
        : "=r"(r[0]), "=r"(r[1]), "=r"(r[2]), "=r"(r[3]) : "r"(a));
}
__device__ __forceinline__ void ldsm2(uint32_t* r, uint32_t a) {
    asm volatile("ldmatrix.sync.aligned.m8n8.x2.shared.b16 {%0,%1}, [%2];"
        : "=r"(r[0]), "=r"(r[1]) : "r"(a));
}
__device__ __forceinline__ void mma16816(float* d, const uint32_t* a, const uint32_t* b) {
    asm volatile("mma.sync.aligned.m16n8k16.row.col.f32.f16.f16.f32 "
        "{%0,%1,%2,%3}, {%4,%5,%6,%7}, {%8,%9}, {%0,%1,%2,%3};"
        : "+f"(d[0]), "+f"(d[1]), "+f"(d[2]), "+f"(d[3])
        : "r"(a[0]), "r"(a[1]), "r"(a[2]), "r"(a[3]), "r"(b[0]), "r"(b[1]));
}

// ---------------- input MLP (fp16 outputs) -------------------------------------
__global__ __launch_bounds__(256) void k_input(
    const float* __restrict__ x,
    const float* __restrict__ Wp, const float* __restrict__ bp,
    const float* __restrict__ W1, const float* __restrict__ b1,
    const float* __restrict__ W2, const float* __restrict__ b2)
{
    __shared__ float sWp[Ff * Pp], sbp[Pp];
    __shared__ float sW1[Pp * Cc], sb1[Cc];
    __shared__ float sW2[Pp * Cc], sb2[Cc];
    __shared__ float sx[16 * Ff], shp[16 * Pp];
    int t = threadIdx.x;
    for (int i = t; i < Ff * Pp; i += 256) sWp[i] = Wp[i];
    if (t < Pp) sbp[t] = bp[t];
    for (int i = t; i < Pp * Cc; i += 256) { sW1[i] = W1[i]; sW2[i] = W2[i]; }
    if (t < Cc) { sb1[t] = b1[t]; sb2[t] = b2[t]; }

    int nb = blockIdx.x * 16;
    int nrem = min(16, Nn - nb);
    __syncthreads();

    if (t < nrem * Ff) sx[t] = x[nb * Ff + t];
    __syncthreads();

    #pragma unroll
    for (int q = 0; q < 2; q++) {
        int idx = t + 256 * q;
        int node = idx >> 5, p = idx & 31;
        if (node < nrem) {
            float s = sbp[p];
            #pragma unroll
            for (int k = 0; k < Ff; k++) s += sx[node * Ff + k] * sWp[k * Pp + p];
            shp[idx] = fmaxf(s, 0.f);
        }
    }
    __syncthreads();

    int ch = (t & 63) * 2;
    #pragma unroll
    for (int it = 0; it < 4; it++) {
        int nl = (t >> 6) + 4 * it;
        if (nl < nrem) {
            float s1a = sb1[ch], s1b = sb1[ch + 1];
            float s2a = sb2[ch], s2b = sb2[ch + 1];
            #pragma unroll
            for (int k = 0; k < Pp; k++) {
                float hk = shp[nl * Pp + k];
                s1a += hk * sW1[k * Cc + ch];
                s1b += hk * sW1[k * Cc + ch + 1];
                s2a += hk * sW2[k * Cc + ch];
                s2b += hk * sW2[k * Cc + ch + 1];
            }
            size_t o = (size_t)(nb + nl) * Cc + ch;
            *(__half2*)(g_id + o) = __floats2half2_rn(fmaxf(s1a, 0.f), fmaxf(s1b, 0.f));
            *(__half2*)(g_h  + o) = __floats2half2_rn(fmaxf(s2a, 0.f), fmaxf(s2b, 0.f));
        }
    }
}

// ---------------- weight prep: transpose + fp16 -------------------------------
__global__ void k_prepw(const float* __restrict__ gW, const float* __restrict__ fW,
                        const float* __restrict__ l1W)
{
    int idx = blockIdx.x * 256 + threadIdx.x;
    float v;
    __half* dst;
    size_t o;
    if (idx < Ll * Cc * Cc) {
        int l = idx >> 14, r = idx & 16383;
        int n = r >> 7, k = r & 127;
        v = gW[(size_t)l * 16384 + (size_t)k * 128 + n];
        o = (size_t)l * 16384 + (size_t)n * 128 + k;
        dst = g_wg;
    } else if (idx < Ll * Cc * Cc + Ll * 2 * Cc * Cc) {
        int j = idx - Ll * Cc * Cc;
        int l = j >> 15, r = j & 32767;
        int n = r >> 8, k = r & 255;
        v = fW[(size_t)l * 32768 + (size_t)k * 128 + n];
        o = (size_t)l * 32768 + (size_t)n * 256 + k;
        dst = g_wf;
    } else {
        int j = idx - (Ll * Cc * Cc + Ll * 2 * Cc * Cc);
        int n = j >> 8, k = j & 255;
        v = l1W[(size_t)k * 128 + n];
        o = (size_t)n * 256 + k;
        dst = g_wl;
    }
    dst[o] = __float2half(v);
}

// ---------------- fp16 HMMA GEMM, persistent, W-resident ----------------------
// out = act(A@W + b);  A=[A1;A2] fp16, W fp16 [n][K].
// flags: 1=relu, 2=bias, 8=fp16 out (outh), else fp32 out (outf)
#define PADK 72
#define ASTG (128 * PADK * 2)
__device__ __forceinline__ void issueA(
    int it, int nch, int bid, uint32_t uA,
    const __half* A1, const __half* A2, int tid)
{
    int j = it / nch, ch = it % nch;
    int row0 = (bid + j * TG_GRID) * 128;
    const __half* A = (ch * 64 < Cc) ? A1 : A2;
    int kA = (ch * 64) & (Cc - 1);
    uint32_t sb = uA + (uint32_t)(it & 1) * ASTG;
    #pragma unroll
    for (int q = 0; q < 2; q++) {
        int i = tid + 512 * q;
        int r = i >> 3, k8 = (i & 7) * 8;
        uint32_t doff = (uint32_t)((r * PADK + k8) << 1);
        int grow = row0 + r;
        uint32_t sz = (grow < Nn) ? 16u : 0u;
        cp16(sb + doff, A + (size_t)grow * Cc + kA + k8, sz);
    }
    asm volatile("cp.async.commit_group;");
}

__global__ __launch_bounds__(512) void k_tgemm(
    const __half* __restrict__ A1, const __half* __restrict__ A2,
    const __half* __restrict__ Wh,
    const float* __restrict__ bias, float* __restrict__ outf,
    __half* __restrict__ outh, int K, int flags)
{
    extern __shared__ char sm[];
    int PADW = K + 8;
    uint32_t SWB = (uint32_t)(128 * PADW * 2);
    uint32_t uW = smem_u32(sm);
    uint32_t uA = uW + SWB;

    int tid = threadIdx.x;
    int wid = tid >> 5, lane = tid & 31;
    int wm = wid & 3, wn = wid >> 2;
    int rim = lane & 7, mid = lane >> 3;
    int bid = blockIdx.x;

    int wq = (K >> 3);
    for (int i = tid; i < 128 * wq; i += 512) {
        int n = i / wq, k8 = (i % wq) * 8;
        cp16(uW + (uint32_t)((n * PADW + k8) << 1), Wh + (size_t)n * K + k8, 16u);
    }
    asm volatile("cp.async.commit_group;");

    uint32_t aBase[2], bBase[4];
    #pragma unroll
    for (int mt = 0; mt < 2; mt++) {
        int r = wm * 32 + mt * 16 + rim + (mid & 1) * 8;
        int c = (mid >> 1) * 8;
        aBase[mt] = uA + (uint32_t)((r * PADK + c) << 1);
    }
    #pragma unroll
    for (int nt = 0; nt < 4; nt++) {
        int r = wn * 32 + nt * 8 + rim;
        int c = (mid & 1) * 8;
        bBase[nt] = uW + (uint32_t)((r * PADW + c) << 1);
    }

    int nch = K >> 6;
    int nt_cta = (NT - bid + TG_GRID - 1) / TG_GRID;
    int niter = nt_cta * nch;
    if (niter <= 0) return;

    float acc[2][4][4];
    #pragma unroll
    for (int mt = 0; mt < 2; mt++)
        #pragma unroll
        for (int nt = 0; nt < 4; nt++)
            #pragma unroll
            for (int q = 0; q < 4; q++) acc[mt][nt][q] = 0.f;

    issueA(0, nch, bid, uA, A1, A2, tid);

    for (int it = 0; it < niter; it++) {
        int ch = it % nch;
        if (it + 1 < niter) {
            issueA(it + 1, nch, bid, uA, A1, A2, tid);
            asm volatile("cp.async.wait_group 1;");
        } else {
            asm volatile("cp.async.wait_group 0;");
        }
        __syncthreads();

        uint32_t sA = (uint32_t)(it & 1) * ASTG;
        uint32_t kwb = (uint32_t)((ch * 64) << 1);
        #pragma unroll
        for (int ks = 0; ks < 4; ks++) {
            uint32_t ka = (uint32_t)ks * 32;
            uint32_t kw = kwb + (uint32_t)ks * 32;
            uint32_t ah[2][4];
            ldsm4(ah[0], aBase[0] + sA + ka);
            ldsm4(ah[1], aBase[1] + sA + ka);
            #pragma unroll
            for (int nt = 0; nt < 4; nt++) {
                uint32_t bh[2];
                ldsm2(bh, bBase[nt] + kw);
                mma16816(acc[0][nt], ah[0], bh);
                mma16816(acc[1][nt], ah[1], bh);
            }
        }

        if (ch == nch - 1) {
            int row0 = (bid + (it / nch) * TG_GRID) * 128;
            int gr = row0 + wm * 32 + (lane >> 2);
            int gc = wn * 32 + (lane & 3) * 2;
            #pragma unroll
            for (int nt = 0; nt < 4; nt++) {
                int col = gc + nt * 8;
                float2 b2 = make_float2(0.f, 0.f);
                if (flags & 2) b2 = *(const float2*)(bias + col);
                #pragma unroll
                for (int mt = 0; mt < 2; mt++) {
                    #pragma unroll
                    for (int hf = 0; hf < 2; hf++) {
                        int r = gr + mt * 16 + hf * 8;
                        if (r < Nn) {
                            float v0 = acc[mt][nt][2 * hf + 0] + b2.x;
                            float v1 = acc[mt][nt][2 * hf + 1] + b2.y;
                            if (flags & 1) { v0 = fmaxf(v0, 0.f); v1 = fmaxf(v1, 0.f); }
                            size_t o = (size_t)r * Cc + col;
                            if (flags & 8) {
                                *(__half2*)(outh + o) = __floats2half2_rn(v0, v1);
                            } else {
                                *(float2*)(outf + o) = make_float2(v0, v1);
                            }
                        }
                    }
                }
            }
            #pragma unroll
            for (int mt = 0; mt < 2; mt++)
                #pragma unroll
                for (int nt = 0; nt < 4; nt++)
                    #pragma unroll
                    for (int q = 0; q < 4; q++) acc[mt][nt][q] = 0.f;
        }
        __syncthreads();
    }
}

// ---------------- FUSED fcg + next-layer gcn GEMM ------------------------------
// h = relu([id, ag] @ Wf + fb) (kept in smem); hw = h @ Wg  -> global (fp16)
// smem: Wf 128x264 (67584B) | A ring 2x18432 (36864B) | Wg 128x136 (34816B) | htile 128x136 (34816B)
#define PADH 136
#define OF_WG 104448
#define OF_HT 139264
#define FS_SMEM 174080
__global__ __launch_bounds__(512) void k_fused(
    const __half* __restrict__ idA, const __half* __restrict__ agA,
    const __half* __restrict__ Wf, const float* __restrict__ fbias,
    const __half* __restrict__ Wg, __half* __restrict__ hwout)
{
    extern __shared__ char sm[];
    const int K = 256, PADW = 264;
    uint32_t uW = smem_u32(sm);
    uint32_t uA = uW + 128 * PADW * 2;
    uint32_t uG = uW + OF_WG;
    uint32_t uH = uW + OF_HT;

    int tid = threadIdx.x;
    int wid = tid >> 5, lane = tid & 31;
    int wm = wid & 3, wn = wid >> 2;
    int rim = lane & 7, mid = lane >> 3;
    int bid = blockIdx.x;

    // load Wf + Wg once (same first group)
    for (int i = tid; i < 128 * 32; i += 512) {
        int n = i >> 5, k8 = (i & 31) * 8;
        cp16(uW + (uint32_t)((n * PADW + k8) << 1), Wf + (size_t)n * K + k8, 16u);
    }
    for (int i = tid; i < 128 * 16; i += 512) {
        int n = i >> 4, k8 = (i & 15) * 8;
        cp16(uG + (uint32_t)((n * PADH + k8) << 1), Wg + (size_t)n * Cc + k8, 16u);
    }
    asm volatile("cp.async.commit_group;");

    uint32_t aBase[2], bBase[4], hBase[2], gBase[4];
    #pragma unroll
    for (int mt = 0; mt < 2; mt++) {
        int r = wm * 32 + mt * 16 + rim + (mid & 1) * 8;
        int c = (mid >> 1) * 8;
        aBase[mt] = uA + (uint32_t)((r * PADK + c) << 1);
        hBase[mt] = uH + (uint32_t)((r * PADH + c) << 1);
    }
    #pragma unroll
    for (int nt = 0; nt < 4; nt++) {
        int r = wn * 32 + nt * 8 + rim;
        int c = (mid & 1) * 8;
        bBase[nt] = uW + (uint32_t)((r * PADW + c) << 1);
        gBase[nt] = uG + (uint32_t)((r * PADH + c) << 1);
    }

    const int nch = 4;
    int nt_cta = (NT - bid + TG_GRID - 1) / TG_GRID;
    int niter = nt_cta * nch;
    if (niter <= 0) return;

    float acc[2][4][4];
    #pragma unroll
    for (int mt = 0; mt < 2; mt++)
        #pragma unroll
        for (int nt = 0; nt < 4; nt++)
            #pragma unroll
            for (int q = 0; q < 4; q++) acc[mt][nt][q] = 0.f;

    issueA(0, nch, bid, uA, idA, agA, tid);

    for (int it = 0; it < niter; it++) {
        int ch = it % nch;
        if (it + 1 < niter) {
            issueA(it + 1, nch, bid, uA, idA, agA, tid);
            asm volatile("cp.async.wait_group 1;");
        } else {
            asm volatile("cp.async.wait_group 0;");
        }
        __syncthreads();

        uint32_t sA = (uint32_t)(it & 1) * ASTG;
        uint32_t kwb = (uint32_t)((ch * 64) << 1);
        #pragma unroll
        for (int ks = 0; ks < 4; ks++) {
            uint32_t ka = (uint32_t)ks * 32;
            uint32_t kw = kwb + (uint32_t)ks * 32;
            uint32_t ah[2][4];
            ldsm4(ah[0], aBase[0] + sA + ka);
            ldsm4(ah[1], aBase[1] + sA + ka);
            #pragma unroll
            for (int nt = 0; nt < 4; nt++) {
                uint32_t bh[2];
                ldsm2(bh, bBase[nt] + kw);
                mma16816(acc[0][nt], ah[0], bh);
                mma16816(acc[1][nt], ah[1], bh);
            }
        }

        if (ch == nch - 1) {
            int row0 = (bid + (it / nch) * TG_GRID) * 128;
            int lr = wm * 32 + (lane >> 2);
            int gc = wn * 32 + (lane & 3) * 2;
            // ---- epilogue1: h = relu(acc + fb) -> smem htile (fp16) ----
            char* pH = sm + OF_HT;
            #pragma unroll
            for (int nt = 0; nt < 4; nt++) {
                int col = gc + nt * 8;
                float2 b2 = *(const float2*)(fbias + col);
                #pragma unroll
                for (int mt = 0; mt < 2; mt++) {
                    #pragma unroll
                    for (int hf = 0; hf < 2; hf++) {
                        int r = lr + mt * 16 + hf * 8;
                        float v0 = fmaxf(acc[mt][nt][2 * hf + 0] + b2.x, 0.f);
                        float v1 = fmaxf(acc[mt][nt][2 * hf + 1] + b2.y, 0.f);
                        *(__half2*)(pH + ((r * PADH + col) << 1)) = __floats2half2_rn(v0, v1);
                    }
                }
            }
            __syncthreads();

            // ---- GEMM2: hw = htile @ Wg ----
            #pragma unroll
            for (int mt = 0; mt < 2; mt++)
                #pragma unroll
                for (int nt = 0; nt < 4; nt++)
                    #pragma unroll
                    for (int q = 0; q < 4; q++) acc[mt][nt][q] = 0.f;
            #pragma unroll
            for (int ks = 0; ks < 8; ks++) {
                uint32_t ka = (uint32_t)ks * 32;
                uint32_t ah[2][4];
                ldsm4(ah[0], hBase[0] + ka);
                ldsm4(ah[1], hBase[1] + ka);
                #pragma unroll
                for (int nt = 0; nt < 4; nt++) {
                    uint32_t bh[2];
                    ldsm2(bh, gBase[nt] + ka);
                    mma16816(acc[0][nt], ah[0], bh);
                    mma16816(acc[1][nt], ah[1], bh);
                }
            }
            // ---- epilogue2: hw -> global fp16 (no bias/relu) ----
            int gr = row0 + lr;
            #pragma unroll
            for (int nt = 0; nt < 4; nt++) {
                int col = gc + nt * 8;
                #pragma unroll
                for (int mt = 0; mt < 2; mt++) {
                    #pragma unroll
                    for (int hf = 0; hf < 2; hf++) {
                        int r = gr + mt * 16 + hf * 8;
                        if (r < Nn) {
                            *(__half2*)(hwout + (size_t)r * Cc + col) =
                                __floats2half2_rn(acc[mt][nt][2 * hf + 0],
                                                  acc[mt][nt][2 * hf + 1]);
                        }
                    }
                }
            }
            #pragma unroll
            for (int mt = 0; mt < 2; mt++)
                #pragma unroll
                for (int nt = 0; nt < 4; nt++)
                    #pragma unroll
                    for (int q = 0; q < 4; q++) acc[mt][nt][q] = 0.f;
        }
        __syncthreads();
    }
}

// ---------------- CSR build ---------------------------------------------------
__global__ void k_zero_cnt() {
    for (int i = blockIdx.x * blockDim.x + threadIdx.x; i < Nn; i += gridDim.x * blockDim.x)
        g_cnt[i] = 0;
}
__global__ void k_hist(const int* __restrict__ dst) {
    for (int e = blockIdx.x * blockDim.x + threadIdx.x; e < Ee; e += gridDim.x * blockDim.x)
        atomicAdd(&g_cnt[dst[e]], 1);
}
#define SCHUNK 196
__global__ __launch_bounds__(256) void k_scan1() {
    __shared__ int s[256];
    int t = threadIdx.x, b = blockIdx.x;
    int i = b * SCHUNK + t;
    int v = (t < SCHUNK && i < Nn) ? g_cnt[i] : 0;
    s[t] = v; __syncthreads();
    for (int st = 128; st > 0; st >>= 1) {
        if (t < st) s[t] += s[t + st];
        __syncthreads();
    }
    if (t == 0) g_part[b] = s[0];
}
__global__ __launch_bounds__(256) void k_scan2() {
    __shared__ int s[256];
    int t = threadIdx.x;
    int v = g_part[t];
    s[t] = v; __syncthreads();
    for (int st = 1; st < 256; st <<= 1) {
        int x = (t >= st) ? s[t - st] : 0;
        __syncthreads();
        s[t] += x;
        __syncthreads();
    }
    g_part[t] = s[t] - v;
}
__global__ __launch_bounds__(256) void k_scan3() {
    __shared__ int s[256];
    int t = threadIdx.x, b = blockIdx.x;
    int i = b * SCHUNK + t;
    int valid = (t < SCHUNK && i < Nn);
    int v = valid ? g_cnt[i] : 0;
    s[t] = v; __syncthreads();
    for (int st = 1; st < 256; st <<= 1) {
        int x = (t >= st) ? s[t - st] : 0;
        __syncthreads();
        s[t] += x;
        __syncthreads();
    }
    if (valid) {
        int rp = g_part[b] + s[t] - v;
        g_rowptr[i] = rp;
        g_pos[i] = rp;
    }
    if (b == 0 && t == 0) g_rowptr[Nn] = Ee;
}
__global__ void k_scatter(const int* __restrict__ src, const int* __restrict__ dst,
                          const float* __restrict__ w) {
    for (int e = blockIdx.x * blockDim.x + threadIdx.x; e < Ee; e += gridDim.x * blockDim.x) {
        int d = dst[e];
        int p = atomicAdd(&g_pos[d], 1);
        g_srcs[p] = src[e];
        g_ws[p] = w[e];
    }
}

// ---------------- SpMM (fp16 in/out) fused bias+relu ---------------------------
__global__ __launch_bounds__(256) void k_spmm(const __half* __restrict__ hw,
                                              const float* __restrict__ bias)
{
    int node = blockIdx.x * 8 + (threadIdx.x >> 5);
    int lane = threadIdx.x & 31;
    if (node >= Nn) return;
    int s = g_rowptr[node], e = g_rowptr[node + 1];
    float4 acc = make_float4(0.f, 0.f, 0.f, 0.f);
    for (int p = s; p < e; p += 32) {
        int src = 0; float w = 0.f;
        if (p + lane < e) { src = g_srcs[p + lane]; w = g_ws[p + lane]; }
        int cnt = min(32, e - p);
        for (int j = 0; j < cnt; j++) {
            int sj  = __shfl_sync(0xffffffffu, src, j);
            float wj = __shfl_sync(0xffffffffu, w, j);
            const __half2* row = (const __half2*)(hw + (size_t)sj * Cc + lane * 4);
            float2 v01 = __half22float2(row[0]);
            float2 v23 = __half22float2(row[1]);
            acc.x += v01.x * wj; acc.y += v01.y * wj;
            acc.z += v23.x * wj; acc.w += v23.y * wj;
        }
    }
    float4 b4 = *(const float4*)&bias[lane * 4];
    acc.x = fmaxf(acc.x + b4.x, 0.f);
    acc.y = fmaxf(acc.y + b4.y, 0.f);
    acc.z = fmaxf(acc.z + b4.z, 0.f);
    acc.w = fmaxf(acc.w + b4.w, 0.f);
    size_t o = (size_t)node * Cc + lane * 4;
    *(__half2*)(g_ag + o)     = __floats2half2_rn(acc.x, acc.y);
    *(__half2*)(g_ag + o + 2) = __floats2half2_rn(acc.z, acc.w);
}

// ---------------- final projection + sigmoid ---------------------------------
__global__ __launch_bounds__(256) void k_last2(const float* __restrict__ h,
                                               const float* __restrict__ W2,
                                               const float* __restrict__ b2,
                                               float* __restrict__ out)
{
    int node = blockIdx.x * 8 + (threadIdx.x >> 5);
    int lane = threadIdx.x & 31;
    if (node >= Nn) return;
    float4 v = *(const float4*)&h[(size_t)node * Cc + lane * 4];
    float hv[4] = {v.x, v.y, v.z, v.w};
    float s0 = 0.f, s1 = 0.f;
    #pragma unroll
    for (int q = 0; q < 4; q++) {
        int k = lane * 4 + q;
        s0 += hv[q] * W2[k * 2 + 0];
        s1 += hv[q] * W2[k * 2 + 1];
    }
    #pragma unroll
    for (int o = 16; o > 0; o >>= 1) {
        s0 += __shfl_xor_sync(0xffffffffu, s0, o);
        s1 += __shfl_xor_sync(0xffffffffu, s1, o);
    }
    if (lane == 0) {
        out[node * 2 + 0] = 1.f / (1.f + expf(-(s0 + b2[0])));
        out[node * 2 + 1] = 1.f / (1.f + expf(-(s1 + b2[1])));
    }
}

// ---------------- launch ------------------------------------------------------
extern "C" void kernel_launch(void* const* d_in, const int* in_sizes, int n_in,
                              void* d_out, int out_size)
{
    const float* x    = (const float*)d_in[0];
    const int*   esrc = (const int*)  d_in[1];
    const int*   edst = (const int*)  d_in[2];
    const float* ew   = (const float*)d_in[3];
    const float* pW   = (const float*)d_in[4];
    const float* pb   = (const float*)d_in[5];
    const float* W1   = (const float*)d_in[6];
    const float* b1   = (const float*)d_in[7];
    const float* W2i  = (const float*)d_in[8];
    const float* b2i  = (const float*)d_in[9];
    const float* gW   = (const float*)d_in[10];
    const float* gb   = (const float*)d_in[11];
    const float* fW   = (const float*)d_in[12];
    const float* fb   = (const float*)d_in[13];
    const float* l1W  = (const float*)d_in[14];
    const float* l1b  = (const float*)d_in[15];
    const float* l2W  = (const float*)d_in[16];
    const float* l2b  = (const float*)d_in[17];
    float* out = (float*)d_out;

    const int SMEM128 = 128 * (128 + 8) * 2 + 2 * ASTG;  // 71680
    const int SMEM256 = 128 * (256 + 8) * 2 + 2 * ASTG;  // 104448
    cudaFuncSetAttribute(k_tgemm, cudaFuncAttributeMaxDynamicSharedMemorySize, SMEM256);
    cudaFuncSetAttribute(k_fused, cudaFuncAttributeMaxDynamicSharedMemorySize, FS_SMEM);

    __half* phw;
    float* plast;
    cudaGetSymbolAddress((void**)&phw,   g_hw);
    cudaGetSymbolAddress((void**)&plast, g_last);
    __half *pid, *ph, *pag;
    cudaGetSymbolAddress((void**)&pid, g_id);
    cudaGetSymbolAddress((void**)&ph,  g_h);
    cudaGetSymbolAddress((void**)&pag, g_ag);
    __half *pwg, *pwf, *pwl;
    cudaGetSymbolAddress((void**)&pwg, g_wg);
    cudaGetSymbolAddress((void**)&pwf, g_wf);
    cudaGetSymbolAddress((void**)&pwl, g_wl);

    // launches 0..2, then the profiled 4th launch is the layer-0 GCN GEMM
    k_input<<<(Nn + 15) / 16, 256>>>(x, pW, pb, W1, b1, W2i, b2i);
    k_prepw<<<1280, 256>>>(gW, fW, l1W);
    k_zero_cnt<<<128, 256>>>();
    k_tgemm<<<TG_GRID, 512, SMEM128>>>(ph, ph, pwg,
        (const float*)0, (float*)0, phw, Cc, 8);

    k_hist<<<512, 256>>>(edst);
    k_scan1<<<256, 256>>>();
    k_scan2<<<1, 256>>>();
    k_scan3<<<256, 256>>>();
    k_scatter<<<512, 256>>>(esrc, edst, ew);

    const int GS = (Nn + 7) / 8;
    for (int l = 0; l < Ll; l++) {
        k_spmm<<<GS, 256>>>(phw, gb + (size_t)l * Cc);
        if (l < Ll - 1) {
            // fused: h_{l+1} (smem only) and hw = h_{l+1} @ Wg[l+1]
            k_fused<<<TG_GRID, 512, FS_SMEM>>>(pid, pag,
                pwf + (size_t)l * 2 * Cc * Cc, fb + (size_t)l * Cc,
                pwg + (size_t)(l + 1) * Cc * Cc, phw);
        } else {
            // last layer: write h_6 to global for last1
            k_tgemm<<<TG_GRID, 512, SMEM256>>>(pid, pag,
                pwf + (size_t)l * 2 * Cc * Cc,
                fb + (size_t)l * Cc, (float*)0, ph, 2 * Cc, 11);
        }
    }
    k_tgemm<<<TG_GRID, 512, SMEM256>>>(pid, ph, pwl,
        l1b, plast, (__half*)0, 2 * Cc, 3);
    k_last2<<<GS, 256>>>(plast, l2W, l2b, out);
}

// round 17
// speedup vs baseline: 1.7848x; 1.0715x over previous
#include <cuda_runtime.h>
#include <cuda_fp16.h>
#include <stdint.h>
#include <math.h>

#define Nn 50000
#define Ee 600000
#define Ff 16
#define Pp 32
#define Cc 128
#define Ll 6
#define NT 391
#define TG_GRID 148

__device__ __align__(16) __half g_hw[Nn * Cc];
__device__ __align__(16) __half g_id[Nn * Cc];
__device__ __align__(16) __half g_h[Nn * Cc];
__device__ __align__(16) __half g_ag[Nn * Cc];
__device__ int   g_cnt[Nn];
__device__ int   g_rowptr[Nn + 1];
__device__ int   g_pos[Nn];
__device__ int   g_srcs[Ee];
__device__ float g_ws[Ee];
__device__ int   g_part[256];
__device__ __align__(16) __half g_wg[Ll * Cc * Cc];
__device__ __align__(16) __half g_wf[Ll * 2 * Cc * Cc];
__device__ __align__(16) __half g_wl[2 * Cc * Cc];

__device__ __forceinline__ uint32_t smem_u32(const void* p) {
    uint32_t a;
    asm("{ .reg .u64 t; cvta.to.shared.u64 t, %1; cvt.u32.u64 %0, t; }" : "=r"(a) : "l"(p));
    return a;
}
__device__ __forceinline__ void cp16(uint32_t dst, const void* src, uint32_t srcsize) {
    asm volatile("cp.async.cg.shared.global [%0], [%1], 16, %2;"
                 :: "r"(dst), "l"(src), "r"(srcsize));
}
__device__ __forceinline__ void ldsm4(uint32_t* r, uint32_t a) {
    asm volatile("ldmatrix.sync.aligned.m8n8.x4.shared.b16 {%0,%1,%2,%3}, [%4];"
        : "=r"(r[0]), "=r"(r[1]), "=r"(r[2]), "=r"(r[3]) : "r"(a));
}
__device__ __forceinline__ void ldsm2(uint32_t* r, uint32_t a) {
    asm volatile("ldmatrix.sync.aligned.m8n8.x2.shared.b16 {%0,%1}, [%2];"
        : "=r"(r[0]), "=r"(r[1]) : "r"(a));
}
__device__ __forceinline__ void mma16816(float* d, const uint32_t* a, const uint32_t* b) {
    asm volatile("mma.sync.aligned.m16n8k16.row.col.f32.f16.f16.f32 "
        "{%0,%1,%2,%3}, {%4,%5,%6,%7}, {%8,%9}, {%0,%1,%2,%3};"
        : "+f"(d[0]), "+f"(d[1]), "+f"(d[2]), "+f"(d[3])
        : "r"(a[0]), "r"(a[1]), "r"(a[2]), "r"(a[3]), "r"(b[0]), "r"(b[1]));
}
__device__ __forceinline__ void fma_row(float4& acc, uint2 r, float w) {
    float2 f01 = __half22float2(*(__half2*)&r.x);
    float2 f23 = __half22float2(*(__half2*)&r.y);
    acc.x += f01.x * w; acc.y += f01.y * w;
    acc.z += f23.x * w; acc.w += f23.y * w;
}

__global__ __launch_bounds__(256) void k_input(
    const float* __restrict__ x,
    const float* __restrict__ Wp, const float* __restrict__ bp,
    const float* __restrict__ W1, const float* __restrict__ b1,
    const float* __restrict__ W2, const float* __restrict__ b2)
{
    __shared__ float sWp[Ff * Pp], sbp[Pp];
    __shared__ float sW1[Pp * Cc], sb1[Cc];
    __shared__ float sW2[Pp * Cc], sb2[Cc];
    __shared__ float sx[16 * Ff], shp[16 * Pp];
    int t = threadIdx.x;
    for (int i = t; i < Ff * Pp; i += 256) sWp[i] = Wp[i];
    if (t < Pp) sbp[t] = bp[t];
    for (int i = t; i < Pp * Cc; i += 256) { sW1[i] = W1[i]; sW2[i] = W2[i]; }
    if (t < Cc) { sb1[t] = b1[t]; sb2[t] = b2[t]; }

    int nb = blockIdx.x * 16;
    int nrem = min(16, Nn - nb);
    __syncthreads();

    if (t < nrem * Ff) sx[t] = x[nb * Ff + t];
    __syncthreads();

    #pragma unroll
    for (int q = 0; q < 2; q++) {
        int idx = t + 256 * q;
        int node = idx >> 5, p = idx & 31;
        if (node < nrem) {
            float s = sbp[p];
            #pragma unroll
            for (int k = 0; k < Ff; k++) s += sx[node * Ff + k] * sWp[k * Pp + p];
            shp[idx] = fmaxf(s, 0.f);
        }
    }
    __syncthreads();

    int ch = (t & 63) * 2;
    #pragma unroll
    for (int it = 0; it < 4; it++) {
        int nl = (t >> 6) + 4 * it;
        if (nl < nrem) {
            float s1a = sb1[ch], s1b = sb1[ch + 1];
            float s2a = sb2[ch], s2b = sb2[ch + 1];
            #pragma unroll
            for (int k = 0; k < Pp; k++) {
                float hk = shp[nl * Pp + k];
                s1a += hk * sW1[k * Cc + ch];
                s1b += hk * sW1[k * Cc + ch + 1];
                s2a += hk * sW2[k * Cc + ch];
                s2b += hk * sW2[k * Cc + ch + 1];
            }
            size_t o = (size_t)(nb + nl) * Cc + ch;
            *(__half2*)(g_id + o) = __floats2half2_rn(fmaxf(s1a, 0.f), fmaxf(s1b, 0.f));
            *(__half2*)(g_h  + o) = __floats2half2_rn(fmaxf(s2a, 0.f), fmaxf(s2b, 0.f));
        }
    }
}

__global__ void k_prepw(const float* __restrict__ gW, const float* __restrict__ fW,
                        const float* __restrict__ l1W)
{
    int idx = blockIdx.x * 256 + threadIdx.x;
    if (idx < Nn) g_cnt[idx] = 0;
    float v;
    __half* dst;
    size_t o;
    if (idx < Ll * Cc * Cc) {
        int l = idx >> 14, r = idx & 16383;
        int n = r >> 7, k = r & 127;
        v = gW[(size_t)l * 16384 + (size_t)k * 128 + n];
        o = (size_t)l * 16384 + (size_t)n * 128 + k;
        dst = g_wg;
    } else if (idx < Ll * Cc * Cc + Ll * 2 * Cc * Cc) {
        int j = idx - Ll * Cc * Cc;
        int l = j >> 15, r = j & 32767;
        int n = r >> 8, k = r & 255;
        v = fW[(size_t)l * 32768 + (size_t)k * 128 + n];
        o = (size_t)l * 32768 + (size_t)n * 256 + k;
        dst = g_wf;
    } else {
        int j = idx - (Ll * Cc * Cc + Ll * 2 * Cc * Cc);
        int n = j >> 8, k = j & 255;
        v = l1W[(size_t)k * 128 + n];
        o = (size_t)n * 256 + k;
        dst = g_wl;
    }
    dst[o] = __float2half(v);
}

#define PADK 72
#define ASTG (128 * PADK * 2)
__device__ __forceinline__ void issueA(
    int it, int nch, int bid, uint32_t uA,
    const __half* A1, const __half* A2, int tid)
{
    int j = it / nch, ch = it % nch;
    int row0 = (bid + j * TG_GRID) * 128;
    const __half* A = (ch * 64 < Cc) ? A1 : A2;
    int kA = (ch * 64) & (Cc - 1);
    uint32_t sb = uA + (uint32_t)(it & 1) * ASTG;
    #pragma unroll
    for (int q = 0; q < 2; q++) {
        int i = tid + 512 * q;
        int r = i >> 3, k8 = (i & 7) * 8;
        uint32_t doff = (uint32_t)((r * PADK + k8) << 1);
        int grow = row0 + r;
        uint32_t sz = (grow < Nn) ? 16u : 0u;
        cp16(sb + doff, A + (size_t)grow * Cc + kA + k8, sz);
    }
    asm volatile("cp.async.commit_group;");
}

__global__ __launch_bounds__(512) void k_tgemm(
    const __half* __restrict__ A1, const __half* __restrict__ A2,
    const __half* __restrict__ Wh,
    const float* __restrict__ bias, float* __restrict__ outf,
    __half* __restrict__ outh, int K, int flags)
{
    extern __shared__ char sm[];
    int PADW = K + 8;
    uint32_t SWB = (uint32_t)(128 * PADW * 2);
    uint32_t uW = smem_u32(sm);
    uint32_t uA = uW + SWB;

    int tid = threadIdx.x;
    int wid = tid >> 5, lane = tid & 31;
    int wm = wid & 3, wn = wid >> 2;
    int rim = lane & 7, mid = lane >> 3;
    int bid = blockIdx.x;

    int wq = (K >> 3);
    for (int i = tid; i < 128 * wq; i += 512) {
        int n = i / wq, k8 = (i % wq) * 8;
        cp16(uW + (uint32_t)((n * PADW + k8) << 1), Wh + (size_t)n * K + k8, 16u);
    }
    asm volatile("cp.async.commit_group;");

    uint32_t aBase[2], bBase[4];
    #pragma unroll
    for (int mt = 0; mt < 2; mt++) {
        int r = wm * 32 + mt * 16 + rim + (mid & 1) * 8;
        int c = (mid >> 1) * 8;
        aBase[mt] = uA + (uint32_t)((r * PADK + c) << 1);
    }
    #pragma unroll
    for (int nt = 0; nt < 4; nt++) {
        int r = wn * 32 + nt * 8 + rim;
        int c = (mid & 1) * 8;
        bBase[nt] = uW + (uint32_t)((r * PADW + c) << 1);
    }

    int nch = K >> 6;
    int nt_cta = (NT - bid + TG_GRID - 1) / TG_GRID;
    int niter = nt_cta * nch;
    if (niter <= 0) return;

    float acc[2][4][4];
    #pragma unroll
    for (int mt = 0; mt < 2; mt++)
        #pragma unroll
        for (int nt = 0; nt < 4; nt++)
            #pragma unroll
            for (int q = 0; q < 4; q++) acc[mt][nt][q] = 0.f;

    issueA(0, nch, bid, uA, A1, A2, tid);

    for (int it = 0; it < niter; it++) {
        int ch = it % nch;
        if (it + 1 < niter) {
            issueA(it + 1, nch, bid, uA, A1, A2, tid);
            asm volatile("cp.async.wait_group 1;");
        } else {
            asm volatile("cp.async.wait_group 0;");
        }
        __syncthreads();

        uint32_t sA = (uint32_t)(it & 1) * ASTG;
        uint32_t kwb = (uint32_t)((ch * 64) << 1);
        #pragma unroll
        for (int ks = 0; ks < 4; ks++) {
            uint32_t ka = (uint32_t)ks * 32;
            uint32_t kw = kwb + (uint32_t)ks * 32;
            uint32_t ah[2][4];
            ldsm4(ah[0], aBase[0] + sA + ka);
            ldsm4(ah[1], aBase[1] + sA + ka);
            #pragma unroll
            for (int nt = 0; nt < 4; nt++) {
                uint32_t bh[2];
                ldsm2(bh, bBase[nt] + kw);
                mma16816(acc[0][nt], ah[0], bh);
                mma16816(acc[1][nt], ah[1], bh);
            }
        }

        if (ch == nch - 1) {
            int row0 = (bid + (it / nch) * TG_GRID) * 128;
            int gr = row0 + wm * 32 + (lane >> 2);
            int gc = wn * 32 + (lane & 3) * 2;
            #pragma unroll
            for (int nt = 0; nt < 4; nt++) {
                int col = gc + nt * 8;
                float2 b2 = make_float2(0.f, 0.f);
                if (flags & 2) b2 = *(const float2*)(bias + col);
                #pragma unroll
                for (int mt = 0; mt < 2; mt++) {
                    #pragma unroll
                    for (int hf = 0; hf < 2; hf++) {
                        int r = gr + mt * 16 + hf * 8;
                        if (r < Nn) {
                            float v0 = acc[mt][nt][2 * hf + 0] + b2.x;
                            float v1 = acc[mt][nt][2 * hf + 1] + b2.y;
                            if (flags & 1) { v0 = fmaxf(v0, 0.f); v1 = fmaxf(v1, 0.f); }
                            size_t o = (size_t)r * Cc + col;
                            if (flags & 8) {
                                *(__half2*)(outh + o) = __floats2half2_rn(v0, v1);
                            } else {
                                *(float2*)(outf + o) = make_float2(v0, v1);
                            }
                        }
                    }
                }
            }
            #pragma unroll
            for (int mt = 0; mt < 2; mt++)
                #pragma unroll
                for (int nt = 0; nt < 4; nt++)
                    #pragma unroll
                    for (int q = 0; q < 4; q++) acc[mt][nt][q] = 0.f;
        }
        __syncthreads();
    }
}

#define PADH 136
#define OF_WG 104448
#define OF_HT 139264
#define FS_SMEM 174080
__global__ __launch_bounds__(512) void k_fused(
    const __half* __restrict__ idA, const __half* __restrict__ agA,
    const __half* __restrict__ Wf, const float* __restrict__ fbias,
    const __half* __restrict__ Wg, __half* __restrict__ hwout)
{
    extern __shared__ char sm[];
    const int K = 256, PADW = 264;
    uint32_t uW = smem_u32(sm);
    uint32_t uA = uW + 128 * PADW * 2;
    uint32_t uG = uW + OF_WG;
    uint32_t uH = uW + OF_HT;

    int tid = threadIdx.x;
    int wid = tid >> 5, lane = tid & 31;
    int wm = wid & 3, wn = wid >> 2;
    int rim = lane & 7, mid = lane >> 3;
    int bid = blockIdx.x;

    for (int i = tid; i < 128 * 32; i += 512) {
        int n = i >> 5, k8 = (i & 31) * 8;
        cp16(uW + (uint32_t)((n * PADW + k8) << 1), Wf + (size_t)n * K + k8, 16u);
    }
    for (int i = tid; i < 128 * 16; i += 512) {
        int n = i >> 4, k8 = (i & 15) * 8;
        cp16(uG + (uint32_t)((n * PADH + k8) << 1), Wg + (size_t)n * Cc + k8, 16u);
    }
    asm volatile("cp.async.commit_group;");

    uint32_t aBase[2], bBase[4], hBase[2], gBase[4];
    #pragma unroll
    for (int mt = 0; mt < 2; mt++) {
        int r = wm * 32 + mt * 16 + rim + (mid & 1) * 8;
        int c = (mid >> 1) * 8;
        aBase[mt] = uA + (uint32_t)((r * PADK + c) << 1);
        hBase[mt] = uH + (uint32_t)((r * PADH + c) << 1);
    }
    #pragma unroll
    for (int nt = 0; nt < 4; nt++) {
        int r = wn * 32 + nt * 8 + rim;
        int c = (mid & 1) * 8;
        bBase[nt] = uW + (uint32_t)((r * PADW + c) << 1);
        gBase[nt] = uG + (uint32_t)((r * PADH + c) << 1);
    }

    const int nch = 4;
    int nt_cta = (NT - bid + TG_GRID - 1) / TG_GRID;
    int niter = nt_cta * nch;
    if (niter <= 0) return;

    float acc[2][4][4];
    #pragma unroll
    for (int mt = 0; mt < 2; mt++)
        #pragma unroll
        for (int nt = 0; nt < 4; nt++)
            #pragma unroll
            for (int q = 0; q < 4; q++) acc[mt][nt][q] = 0.f;

    issueA(0, nch, bid, uA, idA, agA, tid);

    for (int it = 0; it < niter; it++) {
        int ch = it % nch;
        if (it + 1 < niter) {
            issueA(it + 1, nch, bid, uA, idA, agA, tid);
            asm volatile("cp.async.wait_group 1;");
        } else {
            asm volatile("cp.async.wait_group 0;");
        }
        __syncthreads();

        uint32_t sA = (uint32_t)(it & 1) * ASTG;
        uint32_t kwb = (uint32_t)((ch * 64) << 1);
        #pragma unroll
        for (int ks = 0; ks < 4; ks++) {
            uint32_t ka = (uint32_t)ks * 32;
            uint32_t kw = kwb + (uint32_t)ks * 32;
            uint32_t ah[2][4];
            ldsm4(ah[0], aBase[0] + sA + ka);
            ldsm4(ah[1], aBase[1] + sA + ka);
            #pragma unroll
            for (int nt = 0; nt < 4; nt++) {
                uint32_t bh[2];
                ldsm2(bh, bBase[nt] + kw);
                mma16816(acc[0][nt], ah[0], bh);
                mma16816(acc[1][nt], ah[1], bh);
            }
        }

        if (ch == nch - 1) {
            int row0 = (bid + (it / nch) * TG_GRID) * 128;
            int lr = wm * 32 + (lane >> 2);
            int gc = wn * 32 + (lane & 3) * 2;
            char* pH = sm + OF_HT;
            #pragma unroll
            for (int nt = 0; nt < 4; nt++) {
                int col = gc + nt * 8;
                float2 b2 = *(const float2*)(fbias + col);
                #pragma unroll
                for (int mt = 0; mt < 2; mt++) {
                    #pragma unroll
                    for (int hf = 0; hf < 2; hf++) {
                        int r = lr + mt * 16 + hf * 8;
                        float v0 = fmaxf(acc[mt][nt][2 * hf + 0] + b2.x, 0.f);
                        float v1 = fmaxf(acc[mt][nt][2 * hf + 1] + b2.y, 0.f);
                        *(__half2*)(pH + ((r * PADH + col) << 1)) = __floats2half2_rn(v0, v1);
                    }
                }
            }
            __syncthreads();

            #pragma unroll
            for (int mt = 0; mt < 2; mt++)
                #pragma unroll
                for (int nt = 0; nt < 4; nt++)
                    #pragma unroll
                    for (int q = 0; q < 4; q++) acc[mt][nt][q] = 0.f;
            #pragma unroll
            for (int ks = 0; ks < 8; ks++) {
                uint32_t ka = (uint32_t)ks * 32;
                uint32_t ah[2][4];
                ldsm4(ah[0], hBase[0] + ka);
                ldsm4(ah[1], hBase[1] + ka);
                #pragma unroll
                for (int nt = 0; nt < 4; nt++) {
                    uint32_t bh[2];
                    ldsm2(bh, gBase[nt] + ka);
                    mma16816(acc[0][nt], ah[0], bh);
                    mma16816(acc[1][nt], ah[1], bh);
                }
            }
            int gr = row0 + lr;
            #pragma unroll
            for (int nt = 0; nt < 4; nt++) {
                int col = gc + nt * 8;
                #pragma unroll
                for (int mt = 0; mt < 2; mt++) {
                    #pragma unroll
                    for (int hf = 0; hf < 2; hf++) {
                        int r = gr + mt * 16 + hf * 8;
                        if (r < Nn) {
                            *(__half2*)(hwout + (size_t)r * Cc + col) =
                                __floats2half2_rn(acc[mt][nt][2 * hf + 0],
                                                  acc[mt][nt][2 * hf + 1]);
                        }
                    }
                }
            }
            #pragma unroll
            for (int mt = 0; mt < 2; mt++)
                #pragma unroll
                for (int nt = 0; nt < 4; nt++)
                    #pragma unroll
                    for (int q = 0; q < 4; q++) acc[mt][nt][q] = 0.f;
        }
        __syncthreads();
    }
}

// ---------------- FUSED last1 + last2 ------------------------------------------
#define LF_SMEM 139264
__global__ __launch_bounds__(512) void k_lastf(
    const __half* __restrict__ idA, const __half* __restrict__ hA,
    const __half* __restrict__ Wl, const float* __restrict__ l1b,
    const float* __restrict__ W2, const float* __restrict__ b2,
    float* __restrict__ out)
{
    extern __shared__ char sm[];
    const int K = 256, PADW = 264;
    uint32_t uW = smem_u32(sm);
    uint32_t uA = uW + 128 * PADW * 2;
    char* pH = sm + OF_WG;

    int tid = threadIdx.x;
    int wid = tid >> 5, lane = tid & 31;
    int wm = wid & 3, wn = wid >> 2;
    int rim = lane & 7, mid = lane >> 3;
    int bid = blockIdx.x;

    for (int i = tid; i < 128 * 32; i += 512) {
        int n = i >> 5, k8 = (i & 31) * 8;
        cp16(uW + (uint32_t)((n * PADW + k8) << 1), Wl + (size_t)n * K + k8, 16u);
    }
    asm volatile("cp.async.commit_group;");

    float w20[4], w21[4];
    #pragma unroll
    for (int q = 0; q < 4; q++) {
        w20[q] = W2[(lane * 4 + q) * 2 + 0];
        w21[q] = W2[(lane * 4 + q) * 2 + 1];
    }
    float bb0 = b2[0], bb1 = b2[1];

    uint32_t aBase[2], bBase[4];
    #pragma unroll
    for (int mt = 0; mt < 2; mt++) {
        int r = wm * 32 + mt * 16 + rim + (mid & 1) * 8;
        int c = (mid >> 1) * 8;
        aBase[mt] = uA + (uint32_t)((r * PADK + c) << 1);
    }
    #pragma unroll
    for (int nt = 0; nt < 4; nt++) {
        int r = wn * 32 + nt * 8 + rim;
        int c = (mid & 1) * 8;
        bBase[nt] = uW + (uint32_t)((r * PADW + c) << 1);
    }

    const int nch = 4;
    int nt_cta = (NT - bid + TG_GRID - 1) / TG_GRID;
    int niter = nt_cta * nch;
    if (niter <= 0) return;

    float acc[2][4][4];
    #pragma unroll
    for (int mt = 0; mt < 2; mt++)
        #pragma unroll
        for (int nt = 0; nt < 4; nt++)
            #pragma unroll
            for (int q = 0; q < 4; q++) acc[mt][nt][q] = 0.f;

    issueA(0, nch, bid, uA, idA, hA, tid);

    for (int it = 0; it < niter; it++) {
        int ch = it % nch;
        if (it + 1 < niter) {
            issueA(it + 1, nch, bid, uA, idA, hA, tid);
            asm volatile("cp.async.wait_group 1;");
        } else {
            asm volatile("cp.async.wait_group 0;");
        }
        __syncthreads();

        uint32_t sA = (uint32_t)(it & 1) * ASTG;
        uint32_t kwb = (uint32_t)((ch * 64) << 1);
        #pragma unroll
        for (int ks = 0; ks < 4; ks++) {
            uint32_t ka = (uint32_t)ks * 32;
            uint32_t kw = kwb + (uint32_t)ks * 32;
            uint32_t ah[2][4];
            ldsm4(ah[0], aBase[0] + sA + ka);
            ldsm4(ah[1], aBase[1] + sA + ka);
            #pragma unroll
            for (int nt = 0; nt < 4; nt++) {
                uint32_t bh[2];
                ldsm2(bh, bBase[nt] + kw);
                mma16816(acc[0][nt], ah[0], bh);
                mma16816(acc[1][nt], ah[1], bh);
            }
        }

        if (ch == nch - 1) {
            int row0 = (bid + (it / nch) * TG_GRID) * 128;
            int lr = wm * 32 + (lane >> 2);
            int gc = wn * 32 + (lane & 3) * 2;
            #pragma unroll
            for (int nt = 0; nt < 4; nt++) {
                int col = gc + nt * 8;
                float2 b2v = *(const float2*)(l1b + col);
                #pragma unroll
                for (int mt = 0; mt < 2; mt++) {
                    #pragma unroll
                    for (int hf = 0; hf < 2; hf++) {
                        int r = lr + mt * 16 + hf * 8;
                        float v0 = fmaxf(acc[mt][nt][2 * hf + 0] + b2v.x, 0.f);
                        float v1 = fmaxf(acc[mt][nt][2 * hf + 1] + b2v.y, 0.f);
                        *(__half2*)(pH + ((r * PADH + col) << 1)) = __floats2half2_rn(v0, v1);
                    }
                }
            }
            __syncthreads();

            #pragma unroll
            for (int jj = 0; jj < 8; jj++) {
                int r = wid + 16 * jj;
                uint2 rv = *(uint2*)(pH + ((r * PADH + lane * 4) << 1));
                float2 f01 = __half22float2(*(__half2*)&rv.x);
                float2 f23 = __half22float2(*(__half2*)&rv.y);
                float s0 = f01.x * w20[0] + f01.y * w20[1] + f23.x * w20[2] + f23.y * w20[3];
                float s1 = f01.x * w21[0] + f01.y * w21[1] + f23.x * w21[2] + f23.y * w21[3];
                #pragma unroll
                for (int o = 16; o > 0; o >>= 1) {
                    s0 += __shfl_xor_sync(0xffffffffu, s0, o);
                    s1 += __shfl_xor_sync(0xffffffffu, s1, o);
                }
                int gr = row0 + r;
                if (lane == 0 && gr < Nn) {
                    out[gr * 2 + 0] = 1.f / (1.f + expf(-(s0 + bb0)));
                    out[gr * 2 + 1] = 1.f / (1.f + expf(-(s1 + bb1)));
                }
            }
            #pragma unroll
            for (int mt = 0; mt < 2; mt++)
                #pragma unroll
                for (int nt = 0; nt < 4; nt++)
                    #pragma unroll
                    for (int q = 0; q < 4; q++) acc[mt][nt][q] = 0.f;
        }
        __syncthreads();
    }
}

__global__ void k_hist(const int* __restrict__ dst) {
    for (int e = blockIdx.x * blockDim.x + threadIdx.x; e < Ee; e += gridDim.x * blockDim.x)
        atomicAdd(&g_cnt[dst[e]], 1);
}
#define SCHUNK 196
__global__ __launch_bounds__(256) void k_scan1() {
    __shared__ int s[256];
    int t = threadIdx.x, b = blockIdx.x;
    int i = b * SCHUNK + t;
    int v = (t < SCHUNK && i < Nn) ? g_cnt[i] : 0;
    s[t] = v; __syncthreads();
    for (int st = 128; st > 0; st >>= 1) {
        if (t < st) s[t] += s[t + st];
        __syncthreads();
    }
    if (t == 0) g_part[b] = s[0];
}
__global__ __launch_bounds__(256) void k_scan2() {
    __shared__ int s[256];
    int t = threadIdx.x;
    int v = g_part[t];
    s[t] = v; __syncthreads();
    for (int st = 1; st < 256; st <<= 1) {
        int x = (t >= st) ? s[t - st] : 0;
        __syncthreads();
        s[t] += x;
        __syncthreads();
    }
    g_part[t] = s[t] - v;
}
__global__ __launch_bounds__(256) void k_scan3() {
    __shared__ int s[256];
    int t = threadIdx.x, b = blockIdx.x;
    int i = b * SCHUNK + t;
    int valid = (t < SCHUNK && i < Nn);
    int v = valid ? g_cnt[i] : 0;
    s[t] = v; __syncthreads();
    for (int st = 1; st < 256; st <<= 1) {
        int x = (t >= st) ? s[t - st] : 0;
        __syncthreads();
        s[t] += x;
        __syncthreads();
    }
    if (valid) {
        int rp = g_part[b] + s[t] - v;
        g_rowptr[i] = rp;
        g_pos[i] = rp;
    }
    if (b == 0 && t == 0) g_rowptr[Nn] = Ee;
}
__global__ void k_scatter(const int* __restrict__ src, const int* __restrict__ dst,
                          const float* __restrict__ w) {
    for (int e = blockIdx.x * blockDim.x + threadIdx.x; e < Ee; e += gridDim.x * blockDim.x) {
        int d = dst[e];
        int p = atomicAdd(&g_pos[d], 1);
        g_srcs[p] = src[e];
        g_ws[p] = w[e];
    }
}

__global__ __launch_bounds__(256) void k_spmm(const __half* __restrict__ hw,
                                              const float* __restrict__ bias)
{
    int node = blockIdx.x * 8 + (threadIdx.x >> 5);
    int lane = threadIdx.x & 31;
    if (node >= Nn) return;
    int s = g_rowptr[node], e = g_rowptr[node + 1];
    float4 acc = make_float4(0.f, 0.f, 0.f, 0.f);
    for (int p = s; p < e; p += 32) {
        int src = 0; float w = 0.f;
        if (p + lane < e) { src = g_srcs[p + lane]; w = g_ws[p + lane]; }
        int cnt = min(32, e - p);
        int j = 0;
        for (; j + 4 <= cnt; j += 4) {
            int s0 = __shfl_sync(0xffffffffu, src, j);
            int s1 = __shfl_sync(0xffffffffu, src, j + 1);
            int s2 = __shfl_sync(0xffffffffu, src, j + 2);
            int s3 = __shfl_sync(0xffffffffu, src, j + 3);
            float w0 = __shfl_sync(0xffffffffu, w, j);
            float w1 = __shfl_sync(0xffffffffu, w, j + 1);
            float w2 = __shfl_sync(0xffffffffu, w, j + 2);
            float w3 = __shfl_sync(0xffffffffu, w, j + 3);
            uint2 r0 = *(const uint2*)(hw + (size_t)s0 * Cc + lane * 4);
            uint2 r1 = *(const uint2*)(hw + (size_t)s1 * Cc + lane * 4);
            uint2 r2 = *(const uint2*)(hw + (size_t)s2 * Cc + lane * 4);
            uint2 r3 = *(const uint2*)(hw + (size_t)s3 * Cc + lane * 4);
            fma_row(acc, r0, w0);
            fma_row(acc, r1, w1);
            fma_row(acc, r2, w2);
            fma_row(acc, r3, w3);
        }
        for (; j < cnt; j++) {
            int sj = __shfl_sync(0xffffffffu, src, j);
            float wj = __shfl_sync(0xffffffffu, w, j);
            uint2 rv = *(const uint2*)(hw + (size_t)sj * Cc + lane * 4);
            fma_row(acc, rv, wj);
        }
    }
    float4 b4 = *(const float4*)&bias[lane * 4];
    acc.x = fmaxf(acc.x + b4.x, 0.f);
    acc.y = fmaxf(acc.y + b4.y, 0.f);
    acc.z = fmaxf(acc.z + b4.z, 0.f);
    acc.w = fmaxf(acc.w + b4.w, 0.f);
    size_t o = (size_t)node * Cc + lane * 4;
    *(__half2*)(g_ag + o)     = __floats2half2_rn(acc.x, acc.y);
    *(__half2*)(g_ag + o + 2) = __floats2half2_rn(acc.z, acc.w);
}

extern "C" void kernel_launch(void* const* d_in, const int* in_sizes, int n_in,
                              void* d_out, int out_size)
{
    const float* x    = (const float*)d_in[0];
    const int*   esrc = (const int*)  d_in[1];
    const int*   edst = (const int*)  d_in[2];
    const float* ew   = (const float*)d_in[3];
    const float* pW   = (const float*)d_in[4];
    const float* pb   = (const float*)d_in[5];
    const float* W1   = (const float*)d_in[6];
    const float* b1   = (const float*)d_in[7];
    const float* W2i  = (const float*)d_in[8];
    const float* b2i  = (const float*)d_in[9];
    const float* gW   = (const float*)d_in[10];
    const float* gb   = (const float*)d_in[11];
    const float* fW   = (const float*)d_in[12];
    const float* fb   = (const float*)d_in[13];
    const float* l1W  = (const float*)d_in[14];
    const float* l1b  = (const float*)d_in[15];
    const float* l2W  = (const float*)d_in[16];
    const float* l2b  = (const float*)d_in[17];
    float* out = (float*)d_out;

    const int SMEM128 = 128 * (128 + 8) * 2 + 2 * ASTG;  // 71680
    const int SMEM256 = 128 * (256 + 8) * 2 + 2 * ASTG;  // 104448
    cudaFuncSetAttribute(k_tgemm, cudaFuncAttributeMaxDynamicSharedMemorySize, SMEM256);
    cudaFuncSetAttribute(k_fused, cudaFuncAttributeMaxDynamicSharedMemorySize, FS_SMEM);
    cudaFuncSetAttribute(k_lastf, cudaFuncAttributeMaxDynamicSharedMemorySize, LF_SMEM);

    __half* phw;
    cudaGetSymbolAddress((void**)&phw, g_hw);
    __half *pid, *ph, *pag;
    cudaGetSymbolAddress((void**)&pid, g_id);
    cudaGetSymbolAddress((void**)&ph,  g_h);
    cudaGetSymbolAddress((void**)&pag, g_ag);
    __half *pwg, *pwf, *pwl;
    cudaGetSymbolAddress((void**)&pwg, g_wg);
    cudaGetSymbolAddress((void**)&pwf, g_wf);
    cudaGetSymbolAddress((void**)&pwl, g_wl);

    // idx 0..2, idx 3 = layer-0 GCN GEMM (profiled)
    k_input<<<(Nn + 15) / 16, 256>>>(x, pW, pb, W1, b1, W2i, b2i);
    k_prepw<<<1280, 256>>>(gW, fW, l1W);
    k_hist<<<512, 256>>>(edst);
    k_tgemm<<<TG_GRID, 512, SMEM128>>>(ph, ph, pwg,
        (const float*)0, (float*)0, phw, Cc, 8);

    k_scan1<<<256, 256>>>();
    k_scan2<<<1, 256>>>();
    k_scan3<<<256, 256>>>();
    k_scatter<<<512, 256>>>(esrc, edst, ew);

    const int GS = (Nn + 7) / 8;
    for (int l = 0; l < Ll; l++) {
        k_spmm<<<GS, 256>>>(phw, gb + (size_t)l * Cc);
        if (l < Ll - 1) {
            k_fused<<<TG_GRID, 512, FS_SMEM>>>(pid, pag,
                pwf + (size_t)l * 2 * Cc * Cc, fb + (size_t)l * Cc,
                pwg + (size_t)(l + 1) * Cc * Cc, phw);
        } else {
            k_tgemm<<<TG_GRID, 512, SMEM256>>>(pid, pag,
                pwf + (size_t)l * 2 * Cc * Cc,
                fb + (size_t)l * Cc, (float*)0, ph, 2 * Cc, 11);
        }
    }
    k_lastf<<<TG_GRID, 512, LF_SMEM>>>(pid, ph, pwl, l1b, l2W, l2b, out);
}